// round 2
// baseline (speedup 1.0000x reference)
#include <cuda_runtime.h>
#include <math.h>

// Problem constants
#define BB   2
#define SS   2048
#define DD   1024
#define HH   16
#define DK   64
#define NROWS (BB*SS)   // 4096

// Scratch (allocation-free rule: device globals)
__device__ float g_Q[NROWS*DD];
__device__ float g_K[NROWS*DD];
__device__ float g_V[NROWS*DD];
__device__ float g_C[NROWS*DD];

// ============================================================================
// SGEMM: C[M,N] = A[M,K] * W[N,K]^T + bias[N]
// Tiles: 128x128x16, 256 threads, 8x8 per-thread register tile.
// ============================================================================
#define GBM 128
#define GBN 128
#define GBK 16

__global__ __launch_bounds__(256)
void sgemm_bias(const float* __restrict__ A, const float* __restrict__ W,
                const float* __restrict__ bias, float* __restrict__ C,
                int M, int N, int K)
{
    __shared__ float As[GBK][GBM];
    __shared__ float Ws[GBK][GBN];

    const int t  = threadIdx.x;
    const int bm = blockIdx.y * GBM;
    const int bn = blockIdx.x * GBN;
    const int tx = t & 15;
    const int ty = t >> 4;
    const int lr = t >> 2;          // 0..63
    const int lc = (t & 3) << 2;    // 0,4,8,12

    float acc[8][8];
#pragma unroll
    for (int i = 0; i < 8; i++)
#pragma unroll
        for (int j = 0; j < 8; j++) acc[i][j] = 0.f;

    for (int k0 = 0; k0 < K; k0 += GBK) {
        __syncthreads();
#pragma unroll
        for (int hh = 0; hh < 2; hh++) {
            const int row = lr + hh * 64;
            float4 av = *(const float4*)(A + (size_t)(bm + row) * K + k0 + lc);
            As[lc + 0][row] = av.x;
            As[lc + 1][row] = av.y;
            As[lc + 2][row] = av.z;
            As[lc + 3][row] = av.w;
            float4 wv = *(const float4*)(W + (size_t)(bn + row) * K + k0 + lc);
            Ws[lc + 0][row] = wv.x;
            Ws[lc + 1][row] = wv.y;
            Ws[lc + 2][row] = wv.z;
            Ws[lc + 3][row] = wv.w;
        }
        __syncthreads();

#pragma unroll
        for (int k = 0; k < GBK; k++) {
            float a[8], bw[8];
            float4 v;
            v = *(const float4*)&As[k][ty * 4];      a[0]=v.x; a[1]=v.y; a[2]=v.z; a[3]=v.w;
            v = *(const float4*)&As[k][64 + ty * 4]; a[4]=v.x; a[5]=v.y; a[6]=v.z; a[7]=v.w;
            v = *(const float4*)&Ws[k][tx * 4];      bw[0]=v.x; bw[1]=v.y; bw[2]=v.z; bw[3]=v.w;
            v = *(const float4*)&Ws[k][64 + tx * 4]; bw[4]=v.x; bw[5]=v.y; bw[6]=v.z; bw[7]=v.w;
#pragma unroll
            for (int i = 0; i < 8; i++)
#pragma unroll
                for (int j = 0; j < 8; j++)
                    acc[i][j] = fmaf(a[i], bw[j], acc[i][j]);
        }
    }

    float4 bv0 = *(const float4*)(bias + bn + tx * 4);
    float4 bv1 = *(const float4*)(bias + bn + 64 + tx * 4);
#pragma unroll
    for (int i = 0; i < 8; i++) {
        const int r = bm + ((i < 4) ? (ty * 4 + i) : (64 + ty * 4 + (i - 4)));
        float4 o0 = make_float4(acc[i][0] + bv0.x, acc[i][1] + bv0.y,
                                acc[i][2] + bv0.z, acc[i][3] + bv0.w);
        float4 o1 = make_float4(acc[i][4] + bv1.x, acc[i][5] + bv1.y,
                                acc[i][6] + bv1.z, acc[i][7] + bv1.w);
        *(float4*)(C + (size_t)r * N + bn + tx * 4)      = o0;
        *(float4*)(C + (size_t)r * N + bn + 64 + tx * 4) = o1;
    }
}

// ============================================================================
// Flash attention (fp32, online softmax).
// Grid: (S/64, H, B). Block: 256 threads (16x16), 4x4 register tiles.
// Q/K stored transposed in smem (conflict-free LDS.128 in GEMM1);
// V and P padded to stride 68 (conflict-free stores/loads in GEMM2).
// ============================================================================
#define PST 68
// floats: Qt 4096 | Kt 4096 | Vs 64*68 | Ps 64*68 | ms 64 ints
#define SM_QT 0
#define SM_KT 4096
#define SM_VS 8192
#define SM_PS (8192 + 64*PST)
#define SM_FLOATS (8192 + 2*64*PST)
#define FLASH_SMEM_BYTES (SM_FLOATS*4 + 64*4)

__global__ __launch_bounds__(256)
void flash_attn(const float* __restrict__ Q, const float* __restrict__ Kg,
                const float* __restrict__ Vg, const int* __restrict__ mask,
                float* __restrict__ O)
{
    extern __shared__ float sm[];
    float* Qt = sm + SM_QT;
    float* Kt = sm + SM_KT;
    float* Vs = sm + SM_VS;
    float* Ps = sm + SM_PS;
    int*   ms = (int*)(sm + SM_FLOATS);

    const int t  = threadIdx.x;
    const int tx = t & 15;
    const int ty = t >> 4;
    const int i0 = blockIdx.x * 64;
    const int h  = blockIdx.y;
    const int b  = blockIdx.z;
    const size_t base = (size_t)b * SS * DD + (size_t)h * DK;

    // Load Q tile transposed: Qt[dk][row]
    {
        const int row = t & 63;
        const int q4  = (t >> 6) * 16;
        const float* src = Q + base + (size_t)(i0 + row) * DD + q4;
#pragma unroll
        for (int c = 0; c < 4; c++) {
            float4 v = *(const float4*)(src + c * 4);
            const int dk = q4 + c * 4;
            Qt[(dk + 0) * 64 + row] = v.x;
            Qt[(dk + 1) * 64 + row] = v.y;
            Qt[(dk + 2) * 64 + row] = v.z;
            Qt[(dk + 3) * 64 + row] = v.w;
        }
    }

    float o[4][4];
    float m_i[4], l_i[4];
#pragma unroll
    for (int i = 0; i < 4; i++) {
        m_i[i] = -INFINITY;
        l_i[i] = 0.f;
#pragma unroll
        for (int j = 0; j < 4; j++) o[i][j] = 0.f;
    }

    const float scale = 0.125f;  // 1/sqrt(64)

    for (int j0 = 0; j0 < SS; j0 += 64) {
        __syncthreads();  // prev GEMM2 done with Ps/Vs; GEMM1 done with Kt; Qt ready (iter 0)

        // K tile transposed: Kt[dk][key]  (uncoalesced gmem, L2-resident; conflict-free STS)
        {
            const int key = t & 63;
            const int q4  = (t >> 6) * 16;
            const float* src = Kg + base + (size_t)(j0 + key) * DD + q4;
#pragma unroll
            for (int c = 0; c < 4; c++) {
                float4 v = *(const float4*)(src + c * 4);
                const int dk = q4 + c * 4;
                Kt[(dk + 0) * 64 + key] = v.x;
                Kt[(dk + 1) * 64 + key] = v.y;
                Kt[(dk + 2) * 64 + key] = v.z;
                Kt[(dk + 3) * 64 + key] = v.w;
            }
        }
        // V tile: Vs[key][dk], coalesced loads, stride-68 stores
        {
#pragma unroll
            for (int p = 0; p < 4; p++) {
                const int vi  = t + p * 256;
                const int key = vi >> 4;
                const int dk  = (vi & 15) * 4;
                float4 v = *(const float4*)(Vg + base + (size_t)(j0 + key) * DD + dk);
                *(float4*)&Vs[key * PST + dk] = v;
            }
        }
        if (t < 64) ms[t] = mask[b * SS + j0 + t];
        __syncthreads();

        // GEMM1: S = Q * K^T
        float s[4][4];
#pragma unroll
        for (int i = 0; i < 4; i++)
#pragma unroll
            for (int j = 0; j < 4; j++) s[i][j] = 0.f;

#pragma unroll 8
        for (int dk = 0; dk < 64; dk++) {
            float4 av = *(const float4*)&Qt[dk * 64 + ty * 4];
            float4 kv = *(const float4*)&Kt[dk * 64 + tx * 4];
            float a[4] = {av.x, av.y, av.z, av.w};
            float kk[4] = {kv.x, kv.y, kv.z, kv.w};
#pragma unroll
            for (int i = 0; i < 4; i++)
#pragma unroll
                for (int j = 0; j < 4; j++)
                    s[i][j] = fmaf(a[i], kk[j], s[i][j]);
        }

        // scale + mask
        int mk[4];
#pragma unroll
        for (int j = 0; j < 4; j++) mk[j] = ms[tx * 4 + j];
#pragma unroll
        for (int i = 0; i < 4; i++)
#pragma unroll
            for (int j = 0; j < 4; j++)
                s[i][j] = (mk[j] == 0) ? -1e9f : s[i][j] * scale;

        // online softmax per row (rows of same ty live in 16 contiguous lanes)
#pragma unroll
        for (int i = 0; i < 4; i++) {
            float mloc = fmaxf(fmaxf(s[i][0], s[i][1]), fmaxf(s[i][2], s[i][3]));
#pragma unroll
            for (int off = 8; off > 0; off >>= 1)
                mloc = fmaxf(mloc, __shfl_xor_sync(0xffffffffu, mloc, off));
            const float mnew  = fmaxf(m_i[i], mloc);
            const float alpha = __expf(m_i[i] - mnew);
            float lloc = 0.f;
#pragma unroll
            for (int j = 0; j < 4; j++) {
                const float p = __expf(s[i][j] - mnew);
                s[i][j] = p;
                lloc += p;
            }
#pragma unroll
            for (int off = 8; off > 0; off >>= 1)
                lloc += __shfl_xor_sync(0xffffffffu, lloc, off);
            l_i[i] = l_i[i] * alpha + lloc;
            m_i[i] = mnew;
#pragma unroll
            for (int j = 0; j < 4; j++) o[i][j] *= alpha;
        }

        // store P: Ps[row][key], stride 68, vectorized
#pragma unroll
        for (int i = 0; i < 4; i++) {
            float4 pv = make_float4(s[i][0], s[i][1], s[i][2], s[i][3]);
            *(float4*)&Ps[(ty * 4 + i) * PST + tx * 4] = pv;
        }
        __syncthreads();

        // GEMM2: O += P * V
#pragma unroll 8
        for (int kk2 = 0; kk2 < 64; kk2++) {
            float a0 = Ps[(ty * 4 + 0) * PST + kk2];
            float a1 = Ps[(ty * 4 + 1) * PST + kk2];
            float a2 = Ps[(ty * 4 + 2) * PST + kk2];
            float a3 = Ps[(ty * 4 + 3) * PST + kk2];
            float4 vv = *(const float4*)&Vs[kk2 * PST + tx * 4];
            o[0][0] = fmaf(a0, vv.x, o[0][0]); o[0][1] = fmaf(a0, vv.y, o[0][1]);
            o[0][2] = fmaf(a0, vv.z, o[0][2]); o[0][3] = fmaf(a0, vv.w, o[0][3]);
            o[1][0] = fmaf(a1, vv.x, o[1][0]); o[1][1] = fmaf(a1, vv.y, o[1][1]);
            o[1][2] = fmaf(a1, vv.z, o[1][2]); o[1][3] = fmaf(a1, vv.w, o[1][3]);
            o[2][0] = fmaf(a2, vv.x, o[2][0]); o[2][1] = fmaf(a2, vv.y, o[2][1]);
            o[2][2] = fmaf(a2, vv.z, o[2][2]); o[2][3] = fmaf(a2, vv.w, o[2][3]);
            o[3][0] = fmaf(a3, vv.x, o[3][0]); o[3][1] = fmaf(a3, vv.y, o[3][1]);
            o[3][2] = fmaf(a3, vv.z, o[3][2]); o[3][3] = fmaf(a3, vv.w, o[3][3]);
        }
    }

    // Epilogue: O / l, write context at [row, h*64 + dk]
#pragma unroll
    for (int i = 0; i < 4; i++) {
        const float inv = 1.f / l_i[i];
        float4 ov = make_float4(o[i][0] * inv, o[i][1] * inv,
                                o[i][2] * inv, o[i][3] * inv);
        *(float4*)(O + base + (size_t)(i0 + ty * 4 + i) * DD + tx * 4) = ov;
    }
}

// ============================================================================
// kernel_launch
// ============================================================================
extern "C" void kernel_launch(void* const* d_in, const int* in_sizes, int n_in,
                              void* d_out, int out_size)
{
    const float* q    = (const float*)d_in[0];
    const float* k    = (const float*)d_in[1];
    const float* v    = (const float*)d_in[2];
    const int*   mask = (const int*)  d_in[3];
    const float* wq   = (const float*)d_in[4];
    const float* bq   = (const float*)d_in[5];
    const float* wk   = (const float*)d_in[6];
    const float* bk   = (const float*)d_in[7];
    const float* wv   = (const float*)d_in[8];
    const float* bv   = (const float*)d_in[9];
    const float* wo   = (const float*)d_in[10];
    const float* bo   = (const float*)d_in[11];
    float* out = (float*)d_out;

    float *gQ, *gK, *gV, *gC;
    cudaGetSymbolAddress((void**)&gQ, g_Q);
    cudaGetSymbolAddress((void**)&gK, g_K);
    cudaGetSymbolAddress((void**)&gV, g_V);
    cudaGetSymbolAddress((void**)&gC, g_C);

    static bool attr_set = false;
    if (!attr_set) {
        cudaFuncSetAttribute(flash_attn, cudaFuncAttributeMaxDynamicSharedMemorySize,
                             FLASH_SMEM_BYTES);
        attr_set = true;
    }

    dim3 ggrid(DD / GBN, NROWS / GBM);   // (8, 32)
    sgemm_bias<<<ggrid, 256>>>(q, wq, bq, gQ, NROWS, DD, DD);
    sgemm_bias<<<ggrid, 256>>>(k, wk, bk, gK, NROWS, DD, DD);
    sgemm_bias<<<ggrid, 256>>>(v, wv, bv, gV, NROWS, DD, DD);

    dim3 fgrid(SS / 64, HH, BB);         // (32, 16, 2)
    flash_attn<<<fgrid, 256, FLASH_SMEM_BYTES>>>(gQ, gK, gV, mask, gC);

    sgemm_bias<<<ggrid, 256>>>(gC, wo, bo, out, NROWS, DD, DD);
}

// round 3
// speedup vs baseline: 1.0256x; 1.0256x over previous
#include <cuda_runtime.h>
#include <math.h>

// Problem constants
#define BB   2
#define SS   2048
#define DD   1024
#define HH   16
#define DK   64
#define NROWS (BB*SS)   // 4096

// Scratch (allocation-free rule: device globals)
__device__ float g_Q[NROWS*DD];
__device__ float g_K[NROWS*DD];
__device__ float g_V[NROWS*DD];
__device__ float g_C[NROWS*DD];

// ---------------------------------------------------------------------------
// Packed fp32x2 helpers (sm_103a FFMA2 path — ptxas never emits these from C++)
// ---------------------------------------------------------------------------
typedef unsigned long long u64;

__device__ __forceinline__ void ffma2(u64& d, u64 a, u64 b) {
    asm("fma.rn.f32x2 %0, %1, %2, %0;" : "+l"(d) : "l"(a), "l"(b));
}
__device__ __forceinline__ u64 mul2(u64 a, u64 b) {
    u64 r; asm("mul.rn.f32x2 %0, %1, %2;" : "=l"(r) : "l"(a), "l"(b)); return r;
}
__device__ __forceinline__ u64 dup2(float x) {
    u64 r; asm("mov.b64 %0, {%1, %1};" : "=l"(r) : "f"(x)); return r;
}
__device__ __forceinline__ void unpack2(u64 v, float& lo, float& hi) {
    asm("mov.b64 {%0, %1}, %2;" : "=f"(lo), "=f"(hi) : "l"(v));
}

// ============================================================================
// SGEMM: C[M,N] = A[M,K] * W[N,K]^T + bias[N]
// Tiles: 128x128x16, 256 threads, 8x8 per-thread register tile, FFMA2 inner.
// ============================================================================
#define GBM 128
#define GBN 128
#define GBK 16

__global__ __launch_bounds__(256, 2)
void sgemm_bias(const float* __restrict__ A, const float* __restrict__ W,
                const float* __restrict__ bias, float* __restrict__ C,
                int M, int N, int K)
{
    __shared__ float As[GBK][GBM];
    __shared__ float Ws[GBK][GBN];

    const int t  = threadIdx.x;
    const int bm = blockIdx.y * GBM;
    const int bn = blockIdx.x * GBN;
    const int tx = t & 15;
    const int ty = t >> 4;
    const int lr = t >> 2;          // 0..63
    const int lc = (t & 3) << 2;    // 0,4,8,12

    u64 acc2[8][4];                 // [i][j2] : j pairs (0,1)(2,3)(4,5)(6,7)
#pragma unroll
    for (int i = 0; i < 8; i++)
#pragma unroll
        for (int j = 0; j < 4; j++) acc2[i][j] = 0ull;

    for (int k0 = 0; k0 < K; k0 += GBK) {
        __syncthreads();
#pragma unroll
        for (int hh = 0; hh < 2; hh++) {
            const int row = lr + hh * 64;
            float4 av = *(const float4*)(A + (size_t)(bm + row) * K + k0 + lc);
            As[lc + 0][row] = av.x;
            As[lc + 1][row] = av.y;
            As[lc + 2][row] = av.z;
            As[lc + 3][row] = av.w;
            float4 wv = *(const float4*)(W + (size_t)(bn + row) * K + k0 + lc);
            Ws[lc + 0][row] = wv.x;
            Ws[lc + 1][row] = wv.y;
            Ws[lc + 2][row] = wv.z;
            Ws[lc + 3][row] = wv.w;
        }
        __syncthreads();

#pragma unroll
        for (int k = 0; k < GBK; k++) {
            float4 v;
            float a[8];
            v = *(const float4*)&As[k][ty * 4];      a[0]=v.x; a[1]=v.y; a[2]=v.z; a[3]=v.w;
            v = *(const float4*)&As[k][64 + ty * 4]; a[4]=v.x; a[5]=v.y; a[6]=v.z; a[7]=v.w;
            ulonglong2 w0 = *(const ulonglong2*)&Ws[k][tx * 4];
            ulonglong2 w1 = *(const ulonglong2*)&Ws[k][64 + tx * 4];
            u64 b2[4] = {w0.x, w0.y, w1.x, w1.y};
            u64 ad[8];
#pragma unroll
            for (int i = 0; i < 8; i++) ad[i] = dup2(a[i]);
#pragma unroll
            for (int i = 0; i < 8; i++)
#pragma unroll
                for (int j = 0; j < 4; j++)
                    ffma2(acc2[i][j], ad[i], b2[j]);
        }
    }

    // Unpack + bias + store
    float4 bv0 = *(const float4*)(bias + bn + tx * 4);
    float4 bv1 = *(const float4*)(bias + bn + 64 + tx * 4);
#pragma unroll
    for (int i = 0; i < 8; i++) {
        float c[8];
#pragma unroll
        for (int j = 0; j < 4; j++) unpack2(acc2[i][j], c[2*j], c[2*j+1]);
        const int r = bm + ((i < 4) ? (ty * 4 + i) : (64 + ty * 4 + (i - 4)));
        float4 o0 = make_float4(c[0] + bv0.x, c[1] + bv0.y, c[2] + bv0.z, c[3] + bv0.w);
        float4 o1 = make_float4(c[4] + bv1.x, c[5] + bv1.y, c[6] + bv1.z, c[7] + bv1.w);
        *(float4*)(C + (size_t)r * N + bn + tx * 4)      = o0;
        *(float4*)(C + (size_t)r * N + bn + 64 + tx * 4) = o1;
    }
}

// ============================================================================
// Flash attention (fp32, online softmax), FFMA2 inner loops.
// Grid: (S/64, H, B). Block: 256 threads (16x16), 4x4 register tiles.
// ============================================================================
#define PST 68
#define SM_QT 0
#define SM_KT 4096
#define SM_VS 8192
#define SM_PS (8192 + 64*PST)
#define SM_FLOATS (8192 + 2*64*PST)
#define FLASH_SMEM_BYTES (SM_FLOATS*4 + 64*4)

__global__ __launch_bounds__(256)
void flash_attn(const float* __restrict__ Q, const float* __restrict__ Kg,
                const float* __restrict__ Vg, const int* __restrict__ mask,
                float* __restrict__ O)
{
    extern __shared__ float sm[];
    float* Qt = sm + SM_QT;
    float* Kt = sm + SM_KT;
    float* Vs = sm + SM_VS;
    float* Ps = sm + SM_PS;
    int*   ms = (int*)(sm + SM_FLOATS);

    const int t  = threadIdx.x;
    const int tx = t & 15;
    const int ty = t >> 4;
    const int i0 = blockIdx.x * 64;
    const int h  = blockIdx.y;
    const int b  = blockIdx.z;
    const size_t base = (size_t)b * SS * DD + (size_t)h * DK;

    // Load Q tile transposed: Qt[dk][row]
    {
        const int row = t & 63;
        const int q4  = (t >> 6) * 16;
        const float* src = Q + base + (size_t)(i0 + row) * DD + q4;
#pragma unroll
        for (int c = 0; c < 4; c++) {
            float4 v = *(const float4*)(src + c * 4);
            const int dk = q4 + c * 4;
            Qt[(dk + 0) * 64 + row] = v.x;
            Qt[(dk + 1) * 64 + row] = v.y;
            Qt[(dk + 2) * 64 + row] = v.z;
            Qt[(dk + 3) * 64 + row] = v.w;
        }
    }

    u64 o2[4][2];            // [i][j2]
    float m_i[4], l_i[4];
#pragma unroll
    for (int i = 0; i < 4; i++) {
        m_i[i] = -INFINITY;
        l_i[i] = 0.f;
        o2[i][0] = 0ull; o2[i][1] = 0ull;
    }

    const float scale = 0.125f;  // 1/sqrt(64)

    for (int j0 = 0; j0 < SS; j0 += 64) {
        __syncthreads();

        // K tile transposed: Kt[dk][key]
        {
            const int key = t & 63;
            const int q4  = (t >> 6) * 16;
            const float* src = Kg + base + (size_t)(j0 + key) * DD + q4;
#pragma unroll
            for (int c = 0; c < 4; c++) {
                float4 v = *(const float4*)(src + c * 4);
                const int dk = q4 + c * 4;
                Kt[(dk + 0) * 64 + key] = v.x;
                Kt[(dk + 1) * 64 + key] = v.y;
                Kt[(dk + 2) * 64 + key] = v.z;
                Kt[(dk + 3) * 64 + key] = v.w;
            }
        }
        // V tile: Vs[key][dk]
        {
#pragma unroll
            for (int p = 0; p < 4; p++) {
                const int vi  = t + p * 256;
                const int key = vi >> 4;
                const int dk  = (vi & 15) * 4;
                float4 v = *(const float4*)(Vg + base + (size_t)(j0 + key) * DD + dk);
                *(float4*)&Vs[key * PST + dk] = v;
            }
        }
        if (t < 64) ms[t] = mask[b * SS + j0 + t];
        __syncthreads();

        // GEMM1: S = Q * K^T  (packed f32x2)
        u64 s2[4][2];
#pragma unroll
        for (int i = 0; i < 4; i++) { s2[i][0] = 0ull; s2[i][1] = 0ull; }

#pragma unroll 8
        for (int dk = 0; dk < 64; dk++) {
            float4 av = *(const float4*)&Qt[dk * 64 + ty * 4];
            ulonglong2 kv2 = *(const ulonglong2*)&Kt[dk * 64 + tx * 4];
            u64 a0 = dup2(av.x), a1 = dup2(av.y), a2 = dup2(av.z), a3 = dup2(av.w);
            ffma2(s2[0][0], a0, kv2.x); ffma2(s2[0][1], a0, kv2.y);
            ffma2(s2[1][0], a1, kv2.x); ffma2(s2[1][1], a1, kv2.y);
            ffma2(s2[2][0], a2, kv2.x); ffma2(s2[2][1], a2, kv2.y);
            ffma2(s2[3][0], a3, kv2.x); ffma2(s2[3][1], a3, kv2.y);
        }

        float s[4][4];
#pragma unroll
        for (int i = 0; i < 4; i++) {
            unpack2(s2[i][0], s[i][0], s[i][1]);
            unpack2(s2[i][1], s[i][2], s[i][3]);
        }

        // scale + mask
        int mk[4];
#pragma unroll
        for (int j = 0; j < 4; j++) mk[j] = ms[tx * 4 + j];
#pragma unroll
        for (int i = 0; i < 4; i++)
#pragma unroll
            for (int j = 0; j < 4; j++)
                s[i][j] = (mk[j] == 0) ? -1e9f : s[i][j] * scale;

        // online softmax per row (rows of same ty live in 16 contiguous lanes)
#pragma unroll
        for (int i = 0; i < 4; i++) {
            float mloc = fmaxf(fmaxf(s[i][0], s[i][1]), fmaxf(s[i][2], s[i][3]));
#pragma unroll
            for (int off = 8; off > 0; off >>= 1)
                mloc = fmaxf(mloc, __shfl_xor_sync(0xffffffffu, mloc, off));
            const float mnew  = fmaxf(m_i[i], mloc);
            const float alpha = __expf(m_i[i] - mnew);
            float lloc = 0.f;
#pragma unroll
            for (int j = 0; j < 4; j++) {
                const float p = __expf(s[i][j] - mnew);
                s[i][j] = p;
                lloc += p;
            }
#pragma unroll
            for (int off = 8; off > 0; off >>= 1)
                lloc += __shfl_xor_sync(0xffffffffu, lloc, off);
            l_i[i] = l_i[i] * alpha + lloc;
            m_i[i] = mnew;
            u64 al = dup2(alpha);
            o2[i][0] = mul2(o2[i][0], al);
            o2[i][1] = mul2(o2[i][1], al);
        }

        // store P: Ps[row][key], stride 68, vectorized
#pragma unroll
        for (int i = 0; i < 4; i++) {
            float4 pv = make_float4(s[i][0], s[i][1], s[i][2], s[i][3]);
            *(float4*)&Ps[(ty * 4 + i) * PST + tx * 4] = pv;
        }
        __syncthreads();

        // GEMM2: O += P * V  (packed f32x2)
#pragma unroll 8
        for (int kk2 = 0; kk2 < 64; kk2++) {
            float a0 = Ps[(ty * 4 + 0) * PST + kk2];
            float a1 = Ps[(ty * 4 + 1) * PST + kk2];
            float a2 = Ps[(ty * 4 + 2) * PST + kk2];
            float a3 = Ps[(ty * 4 + 3) * PST + kk2];
            ulonglong2 vv2 = *(const ulonglong2*)&Vs[kk2 * PST + tx * 4];
            u64 d0 = dup2(a0), d1 = dup2(a1), d2 = dup2(a2), d3 = dup2(a3);
            ffma2(o2[0][0], d0, vv2.x); ffma2(o2[0][1], d0, vv2.y);
            ffma2(o2[1][0], d1, vv2.x); ffma2(o2[1][1], d1, vv2.y);
            ffma2(o2[2][0], d2, vv2.x); ffma2(o2[2][1], d2, vv2.y);
            ffma2(o2[3][0], d3, vv2.x); ffma2(o2[3][1], d3, vv2.y);
        }
    }

    // Epilogue: O / l, write context at [row, h*64 + dk]
#pragma unroll
    for (int i = 0; i < 4; i++) {
        const u64 iv = dup2(1.f / l_i[i]);
        ulonglong2 ov;
        ov.x = mul2(o2[i][0], iv);
        ov.y = mul2(o2[i][1], iv);
        *(ulonglong2*)(O + base + (size_t)(i0 + ty * 4 + i) * DD + tx * 4) = ov;
    }
}

// ============================================================================
// kernel_launch
// ============================================================================
extern "C" void kernel_launch(void* const* d_in, const int* in_sizes, int n_in,
                              void* d_out, int out_size)
{
    const float* q    = (const float*)d_in[0];
    const float* k    = (const float*)d_in[1];
    const float* v    = (const float*)d_in[2];
    const int*   mask = (const int*)  d_in[3];
    const float* wq   = (const float*)d_in[4];
    const float* bq   = (const float*)d_in[5];
    const float* wk   = (const float*)d_in[6];
    const float* bk   = (const float*)d_in[7];
    const float* wv   = (const float*)d_in[8];
    const float* bv   = (const float*)d_in[9];
    const float* wo   = (const float*)d_in[10];
    const float* bo   = (const float*)d_in[11];
    float* out = (float*)d_out;

    float *gQ, *gK, *gV, *gC;
    cudaGetSymbolAddress((void**)&gQ, g_Q);
    cudaGetSymbolAddress((void**)&gK, g_K);
    cudaGetSymbolAddress((void**)&gV, g_V);
    cudaGetSymbolAddress((void**)&gC, g_C);

    static bool attr_set = false;
    if (!attr_set) {
        cudaFuncSetAttribute(flash_attn, cudaFuncAttributeMaxDynamicSharedMemorySize,
                             FLASH_SMEM_BYTES);
        attr_set = true;
    }

    dim3 ggrid(DD / GBN, NROWS / GBM);   // (8, 32)
    sgemm_bias<<<ggrid, 256>>>(q, wq, bq, gQ, NROWS, DD, DD);
    sgemm_bias<<<ggrid, 256>>>(k, wk, bk, gK, NROWS, DD, DD);
    sgemm_bias<<<ggrid, 256>>>(v, wv, bv, gV, NROWS, DD, DD);

    dim3 fgrid(SS / 64, HH, BB);         // (32, 16, 2)
    flash_attn<<<fgrid, 256, FLASH_SMEM_BYTES>>>(gQ, gK, gV, mask, gC);

    sgemm_bias<<<ggrid, 256>>>(gC, wo, bo, out, NROWS, DD, DD);
}

// round 7
// speedup vs baseline: 1.3979x; 1.3630x over previous
#include <cuda_runtime.h>
#include <cuda_bf16.h>
#include <math.h>
#include <stdint.h>

// Problem constants
#define BB   2
#define SS   2048
#define DD   1024
#define HH   16
#define DK   64
#define NROWS (BB*SS)   // 4096

// Scratch (allocation-free rule: device globals)
__device__ float g_Q[NROWS*DD];
__device__ float g_K[NROWS*DD];
__device__ float g_V[NROWS*DD];
__device__ float g_C[NROWS*DD];
__device__ __nv_bfloat16 g_Ahi[NROWS*DD];
__device__ __nv_bfloat16 g_Alo[NROWS*DD];
__device__ __nv_bfloat16 g_Whi[DD*DD];
__device__ __nv_bfloat16 g_Wlo[DD*DD];

typedef unsigned long long u64;

// ---------------------------------------------------------------------------
// Packed fp32x2 helpers
// ---------------------------------------------------------------------------
__device__ __forceinline__ void ffma2(u64& d, u64 a, u64 b) {
    asm("fma.rn.f32x2 %0, %1, %2, %0;" : "+l"(d) : "l"(a), "l"(b));
}
__device__ __forceinline__ u64 mul2(u64 a, u64 b) {
    u64 r; asm("mul.rn.f32x2 %0, %1, %2;" : "=l"(r) : "l"(a), "l"(b)); return r;
}
__device__ __forceinline__ u64 dup2(float x) {
    u64 r; asm("mov.b64 %0, {%1, %1};" : "=l"(r) : "f"(x)); return r;
}
__device__ __forceinline__ void unpack2(u64 v, float& lo, float& hi) {
    asm("mov.b64 {%0, %1}, %2;" : "=f"(lo), "=f"(hi) : "l"(v));
}

// ---------------------------------------------------------------------------
// Base-ISA tensor helpers: ldmatrix + mma.sync (compile for plain sm_103)
// ---------------------------------------------------------------------------
__device__ __forceinline__ uint32_t smem_u32(const void* p) {
    uint32_t a;
    asm("{ .reg .u64 t; cvta.to.shared.u64 t, %1; cvt.u32.u64 %0, t; }" : "=r"(a) : "l"(p));
    return a;
}
__device__ __forceinline__ void ldsm_x4(uint32_t& r0, uint32_t& r1, uint32_t& r2,
                                        uint32_t& r3, uint32_t addr) {
    asm volatile("ldmatrix.sync.aligned.m8n8.x4.shared.b16 {%0,%1,%2,%3}, [%4];"
                 : "=r"(r0), "=r"(r1), "=r"(r2), "=r"(r3) : "r"(addr));
}
__device__ __forceinline__ void ldsm_x2(uint32_t& r0, uint32_t& r1, uint32_t addr) {
    asm volatile("ldmatrix.sync.aligned.m8n8.x2.shared.b16 {%0,%1}, [%2];"
                 : "=r"(r0), "=r"(r1) : "r"(addr));
}
__device__ __forceinline__ void mma_bf16(float& c0, float& c1, float& c2, float& c3,
                                         uint32_t a0, uint32_t a1, uint32_t a2, uint32_t a3,
                                         uint32_t b0, uint32_t b1) {
    asm volatile("mma.sync.aligned.m16n8k16.row.col.f32.bf16.bf16.f32 "
                 "{%0,%1,%2,%3}, {%4,%5,%6,%7}, {%8,%9}, {%0,%1,%2,%3};"
                 : "+f"(c0), "+f"(c1), "+f"(c2), "+f"(c3)
                 : "r"(a0), "r"(a1), "r"(a2), "r"(a3), "r"(b0), "r"(b1));
}

// ============================================================================
// fp32 -> (bf16 hi, bf16 lo) split
// ============================================================================
__global__ __launch_bounds__(256)
void split_bf16(const float* __restrict__ x, __nv_bfloat16* __restrict__ hi,
                __nv_bfloat16* __restrict__ lo, int n4)
{
    int i = blockIdx.x * blockDim.x + threadIdx.x;
    if (i >= n4) return;
    float4 v = ((const float4*)x)[i];
    __nv_bfloat16 h0 = __float2bfloat16(v.x);
    __nv_bfloat16 h1 = __float2bfloat16(v.y);
    __nv_bfloat16 h2 = __float2bfloat16(v.z);
    __nv_bfloat16 h3 = __float2bfloat16(v.w);
    __nv_bfloat16 l0 = __float2bfloat16(v.x - __bfloat162float(h0));
    __nv_bfloat16 l1 = __float2bfloat16(v.y - __bfloat162float(h1));
    __nv_bfloat16 l2 = __float2bfloat16(v.z - __bfloat162float(h2));
    __nv_bfloat16 l3 = __float2bfloat16(v.w - __bfloat162float(h3));
    uint2 hh, ll;
    hh.x = (uint32_t)__bfloat16_as_ushort(h0) | ((uint32_t)__bfloat16_as_ushort(h1) << 16);
    hh.y = (uint32_t)__bfloat16_as_ushort(h2) | ((uint32_t)__bfloat16_as_ushort(h3) << 16);
    ll.x = (uint32_t)__bfloat16_as_ushort(l0) | ((uint32_t)__bfloat16_as_ushort(l1) << 16);
    ll.y = (uint32_t)__bfloat16_as_ushort(l2) | ((uint32_t)__bfloat16_as_ushort(l3) << 16);
    ((uint2*)hi)[i] = hh;
    ((uint2*)lo)[i] = ll;
}

// ============================================================================
// Tensor-core GEMM via mma.sync bf16 split x3:
//   C[M,N] = A[M,K] * B[N,K]^T + bias[N]
// Block tile 128x128, K-chunk 32. 8 warps, warp tile 64x32 (4x4 m16n8k16).
// ============================================================================
#define TBK 32
#define TROW 40   // smem row stride in bf16 (80B): conflict-free ldmatrix

__global__ __launch_bounds__(256)
void gemm_tc(const __nv_bfloat16* __restrict__ Ah, const __nv_bfloat16* __restrict__ Al,
             const __nv_bfloat16* __restrict__ Bh, const __nv_bfloat16* __restrict__ Bl,
             const float* __restrict__ bias, float* __restrict__ C,
             int M, int N, int K)
{
    __shared__ __nv_bfloat16 sAh[128 * TROW];
    __shared__ __nv_bfloat16 sAl[128 * TROW];
    __shared__ __nv_bfloat16 sBh[128 * TROW];
    __shared__ __nv_bfloat16 sBl[128 * TROW];

    const int t   = threadIdx.x;
    const int wid = t >> 5;
    const int lane = t & 31;
    const int m0 = blockIdx.y * 128;
    const int n0 = blockIdx.x * 128;
    const int wm = (wid & 1) * 64;   // warp m-offset within block tile
    const int wn = (wid >> 1) * 32;  // warp n-offset

    const uint32_t uAh = smem_u32(sAh);
    const uint32_t uAl = smem_u32(sAl);
    const uint32_t uBh = smem_u32(sBh);
    const uint32_t uBl = smem_u32(sBl);

    float acc[4][4][4];
#pragma unroll
    for (int i = 0; i < 4; i++)
#pragma unroll
        for (int j = 0; j < 4; j++)
#pragma unroll
            for (int r = 0; r < 4; r++) acc[i][j][r] = 0.f;

    for (int k0 = 0; k0 < K; k0 += TBK) {
        __syncthreads();
        // Load 4 tiles of 128 rows x 32 bf16 (64B/row). 512 uint4 per tile.
#pragma unroll
        for (int p = 0; p < 2; p++) {
            const int idx = t + p * 256;
            const int row = idx >> 2;
            const int c   = idx & 3;           // 16B column
            const size_t ga = (size_t)(m0 + row) * K + k0 + c * 8;
            const size_t gb = (size_t)(n0 + row) * K + k0 + c * 8;
            const int so = row * TROW + c * 8; // bf16 offset
            *(uint4*)(sAh + so) = *(const uint4*)(Ah + ga);
            *(uint4*)(sAl + so) = *(const uint4*)(Al + ga);
            *(uint4*)(sBh + so) = *(const uint4*)(Bh + gb);
            *(uint4*)(sBl + so) = *(const uint4*)(Bl + gb);
        }
        __syncthreads();

#pragma unroll
        for (int ks = 0; ks < 2; ks++) {
            // A fragments: 4 m-atoms, hi+lo
            uint32_t ah[4][4], al[4][4];
#pragma unroll
            for (int ma = 0; ma < 4; ma++) {
                const int row = wm + ma * 16 + (lane & 15);
                const uint32_t off = (uint32_t)(row * TROW * 2 + ks * 32 + (lane >> 4) * 16);
                ldsm_x4(ah[ma][0], ah[ma][1], ah[ma][2], ah[ma][3], uAh + off);
                ldsm_x4(al[ma][0], al[ma][1], al[ma][2], al[ma][3], uAl + off);
            }
            // B fragments: 4 n-atoms, hi+lo
            uint32_t bh[4][2], bl[4][2];
#pragma unroll
            for (int na = 0; na < 4; na++) {
                const int row = wn + na * 8 + (lane & 7);
                const uint32_t off = (uint32_t)(row * TROW * 2 + ks * 32 + ((lane >> 3) & 1) * 16);
                ldsm_x2(bh[na][0], bh[na][1], uBh + off);
                ldsm_x2(bl[na][0], bl[na][1], uBl + off);
            }
            // 3-product split accumulation
#pragma unroll
            for (int ma = 0; ma < 4; ma++)
#pragma unroll
                for (int na = 0; na < 4; na++) {
                    float* c = acc[ma][na];
                    mma_bf16(c[0], c[1], c[2], c[3],
                             ah[ma][0], ah[ma][1], ah[ma][2], ah[ma][3],
                             bh[na][0], bh[na][1]);
                    mma_bf16(c[0], c[1], c[2], c[3],
                             ah[ma][0], ah[ma][1], ah[ma][2], ah[ma][3],
                             bl[na][0], bl[na][1]);
                    mma_bf16(c[0], c[1], c[2], c[3],
                             al[ma][0], al[ma][1], al[ma][2], al[ma][3],
                             bh[na][0], bh[na][1]);
                }
        }
    }

    // Epilogue: d layout per atom: c0,c1 -> (g, 2q),(g, 2q+1); c2,c3 -> (g+8, ...)
    const int g = lane >> 2;
    const int q = lane & 3;
#pragma unroll
    for (int ma = 0; ma < 4; ma++) {
#pragma unroll
        for (int na = 0; na < 4; na++) {
            const int col = n0 + wn + na * 8 + q * 2;
            const float b0 = bias[col], b1 = bias[col + 1];
            const int r0 = m0 + wm + ma * 16 + g;
            float* d0 = C + (size_t)r0 * N + col;
            d0[0] = acc[ma][na][0] + b0;
            d0[1] = acc[ma][na][1] + b1;
            float* d1 = C + (size_t)(r0 + 8) * N + col;
            d1[0] = acc[ma][na][2] + b0;
            d1[1] = acc[ma][na][3] + b1;
        }
    }
}

// ============================================================================
// Flash attention: 128 queries x 128 keys per tile, 256 threads,
// 8x8 per-thread in GEMM1, 8x4 in GEMM2, FFMA2 everywhere.
// ============================================================================
#define PST 132
#define VST 68
#define SM_QT 0                       // 64 x 128
#define SM_KT 8192                    // 64 x 128
#define SM_VS 16384                   // 128 x 68
#define SM_PS (16384 + 128*VST)       // 128 x 132
#define SM_FLOATS (SM_PS + 128*PST)
#define FLASH_SMEM_BYTES (SM_FLOATS*4 + 128*4)

__global__ __launch_bounds__(256, 1)
void flash_attn(const float* __restrict__ Q, const float* __restrict__ Kg,
                const float* __restrict__ Vg, const int* __restrict__ mask,
                float* __restrict__ O)
{
    extern __shared__ float sm[];
    float* Qt = sm + SM_QT;
    float* Kt = sm + SM_KT;
    float* Vs = sm + SM_VS;
    float* Ps = sm + SM_PS;
    int*   ms = (int*)(sm + SM_FLOATS);

    const int t  = threadIdx.x;
    const int tx = t & 15;
    const int ty = t >> 4;
    const int i0 = blockIdx.x * 128;
    const int h  = blockIdx.y;
    const int b  = blockIdx.z;
    const size_t base = (size_t)b * SS * DD + (size_t)h * DK;

    // Load Q tile transposed: Qt[dk][row]
    {
        const int row  = t & 127;
        const int part = t >> 7;
        const float* src = Q + base + (size_t)(i0 + row) * DD + part * 32;
#pragma unroll
        for (int c = 0; c < 8; c++) {
            float4 v = *(const float4*)(src + c * 4);
            const int dk = part * 32 + c * 4;
            Qt[(dk + 0) * 128 + row] = v.x;
            Qt[(dk + 1) * 128 + row] = v.y;
            Qt[(dk + 2) * 128 + row] = v.z;
            Qt[(dk + 3) * 128 + row] = v.w;
        }
    }

    u64 o2[8][2];
    float m_i[8], l_i[8];
#pragma unroll
    for (int i = 0; i < 8; i++) {
        m_i[i] = -INFINITY;
        l_i[i] = 0.f;
        o2[i][0] = 0ull; o2[i][1] = 0ull;
    }

    const float scale = 0.125f;  // 1/sqrt(64)

    for (int j0 = 0; j0 < SS; j0 += 128) {
        __syncthreads();

        // K tile transposed: Kt[dk][key]
        {
            const int key  = t & 127;
            const int part = t >> 7;
            const float* src = Kg + base + (size_t)(j0 + key) * DD + part * 32;
#pragma unroll
            for (int c = 0; c < 8; c++) {
                float4 v = *(const float4*)(src + c * 4);
                const int dk = part * 32 + c * 4;
                Kt[(dk + 0) * 128 + key] = v.x;
                Kt[(dk + 1) * 128 + key] = v.y;
                Kt[(dk + 2) * 128 + key] = v.z;
                Kt[(dk + 3) * 128 + key] = v.w;
            }
        }
        // V tile: Vs[key][dk]
        {
#pragma unroll
            for (int p = 0; p < 8; p++) {
                const int vi  = t + p * 256;
                const int key = vi >> 4;
                const int dk  = (vi & 15) * 4;
                float4 v = *(const float4*)(Vg + base + (size_t)(j0 + key) * DD + dk);
                *(float4*)&Vs[key * VST + dk] = v;
            }
        }
        if (t < 128) ms[t] = mask[b * SS + j0 + t];
        __syncthreads();

        // GEMM1: S[128q x 128k] = Q * K^T, 8x8 per thread, packed f32x2
        u64 s2[8][4];
#pragma unroll
        for (int i = 0; i < 8; i++)
#pragma unroll
            for (int j = 0; j < 4; j++) s2[i][j] = 0ull;

#pragma unroll 4
        for (int dk = 0; dk < 64; dk++) {
            const float* kp = Kt + dk * 128 + tx * 8;
            ulonglong2 kb0 = *(const ulonglong2*)kp;
            ulonglong2 kb1 = *(const ulonglong2*)(kp + 4);
            u64 b2[4] = {kb0.x, kb0.y, kb1.x, kb1.y};
            const float* qp = Qt + dk * 128 + ty * 8;
            float4 a0 = *(const float4*)qp;
            float4 a1 = *(const float4*)(qp + 4);
            float av[8] = {a0.x, a0.y, a0.z, a0.w, a1.x, a1.y, a1.z, a1.w};
#pragma unroll
            for (int i = 0; i < 8; i++) {
                u64 ad = dup2(av[i]);
                ffma2(s2[i][0], ad, b2[0]);
                ffma2(s2[i][1], ad, b2[1]);
                ffma2(s2[i][2], ad, b2[2]);
                ffma2(s2[i][3], ad, b2[3]);
            }
        }

        float s[8][8];
#pragma unroll
        for (int i = 0; i < 8; i++) {
            unpack2(s2[i][0], s[i][0], s[i][1]);
            unpack2(s2[i][1], s[i][2], s[i][3]);
            unpack2(s2[i][2], s[i][4], s[i][5]);
            unpack2(s2[i][3], s[i][6], s[i][7]);
        }

        int mk[8];
#pragma unroll
        for (int j = 0; j < 8; j++) mk[j] = ms[tx * 8 + j];
#pragma unroll
        for (int i = 0; i < 8; i++)
#pragma unroll
            for (int j = 0; j < 8; j++)
                s[i][j] = (mk[j] == 0) ? -1e9f : s[i][j] * scale;

        // online softmax per row (16 lanes of each half-warp share ty)
#pragma unroll
        for (int i = 0; i < 8; i++) {
            float mloc = s[i][0];
#pragma unroll
            for (int j = 1; j < 8; j++) mloc = fmaxf(mloc, s[i][j]);
#pragma unroll
            for (int off = 8; off > 0; off >>= 1)
                mloc = fmaxf(mloc, __shfl_xor_sync(0xffffffffu, mloc, off));
            const float mnew  = fmaxf(m_i[i], mloc);
            const float alpha = __expf(m_i[i] - mnew);
            float lloc = 0.f;
#pragma unroll
            for (int j = 0; j < 8; j++) {
                const float p = __expf(s[i][j] - mnew);
                s[i][j] = p;
                lloc += p;
            }
#pragma unroll
            for (int off = 8; off > 0; off >>= 1)
                lloc += __shfl_xor_sync(0xffffffffu, lloc, off);
            l_i[i] = l_i[i] * alpha + lloc;
            m_i[i] = mnew;
            u64 al = dup2(alpha);
            o2[i][0] = mul2(o2[i][0], al);
            o2[i][1] = mul2(o2[i][1], al);
        }

        // store P: Ps[row][key]
#pragma unroll
        for (int i = 0; i < 8; i++) {
            float* pp = Ps + (ty * 8 + i) * PST + tx * 8;
            *(float4*)pp       = make_float4(s[i][0], s[i][1], s[i][2], s[i][3]);
            *(float4*)(pp + 4) = make_float4(s[i][4], s[i][5], s[i][6], s[i][7]);
        }
        __syncthreads();

        // GEMM2: O[128q x 64dk] += P * V, 8 rows x 4 dk per thread
#pragma unroll 4
        for (int key = 0; key < 128; key++) {
            ulonglong2 vv = *(const ulonglong2*)(Vs + key * VST + tx * 4);
#pragma unroll
            for (int i = 0; i < 8; i++) {
                u64 ad = dup2(Ps[(ty * 8 + i) * PST + key]);
                ffma2(o2[i][0], ad, vv.x);
                ffma2(o2[i][1], ad, vv.y);
            }
        }
    }

    // Epilogue
#pragma unroll
    for (int i = 0; i < 8; i++) {
        const u64 iv = dup2(1.f / l_i[i]);
        ulonglong2 ov;
        ov.x = mul2(o2[i][0], iv);
        ov.y = mul2(o2[i][1], iv);
        *(ulonglong2*)(O + base + (size_t)(i0 + ty * 8 + i) * DD + tx * 4) = ov;
    }
}

// ============================================================================
// kernel_launch
// ============================================================================
extern "C" void kernel_launch(void* const* d_in, const int* in_sizes, int n_in,
                              void* d_out, int out_size)
{
    const float* q    = (const float*)d_in[0];
    const float* k    = (const float*)d_in[1];
    const float* v    = (const float*)d_in[2];
    const int*   mask = (const int*)  d_in[3];
    const float* wq   = (const float*)d_in[4];
    const float* bq   = (const float*)d_in[5];
    const float* wk   = (const float*)d_in[6];
    const float* bk   = (const float*)d_in[7];
    const float* wv   = (const float*)d_in[8];
    const float* bv   = (const float*)d_in[9];
    const float* wo   = (const float*)d_in[10];
    const float* bo   = (const float*)d_in[11];
    float* out = (float*)d_out;

    float *gQ, *gK, *gV, *gC;
    __nv_bfloat16 *ahi, *alo, *whi, *wlo;
    cudaGetSymbolAddress((void**)&gQ, g_Q);
    cudaGetSymbolAddress((void**)&gK, g_K);
    cudaGetSymbolAddress((void**)&gV, g_V);
    cudaGetSymbolAddress((void**)&gC, g_C);
    cudaGetSymbolAddress((void**)&ahi, g_Ahi);
    cudaGetSymbolAddress((void**)&alo, g_Alo);
    cudaGetSymbolAddress((void**)&whi, g_Whi);
    cudaGetSymbolAddress((void**)&wlo, g_Wlo);

    static bool attr_set = false;
    if (!attr_set) {
        cudaFuncSetAttribute(flash_attn, cudaFuncAttributeMaxDynamicSharedMemorySize,
                             FLASH_SMEM_BYTES);
        attr_set = true;
    }

    const int nA4 = NROWS * DD / 4;
    const int nW4 = DD * DD / 4;
    dim3 tgrid(DD / 128, NROWS / 128);   // (8, 32)

    // Q projection
    split_bf16<<<nA4 / 256, 256>>>(q, ahi, alo, nA4);
    split_bf16<<<nW4 / 256, 256>>>(wq, whi, wlo, nW4);
    gemm_tc<<<tgrid, 256>>>(ahi, alo, whi, wlo, bq, gQ, NROWS, DD, DD);
    // K projection
    split_bf16<<<nA4 / 256, 256>>>(k, ahi, alo, nA4);
    split_bf16<<<nW4 / 256, 256>>>(wk, whi, wlo, nW4);
    gemm_tc<<<tgrid, 256>>>(ahi, alo, whi, wlo, bk, gK, NROWS, DD, DD);
    // V projection
    split_bf16<<<nA4 / 256, 256>>>(v, ahi, alo, nA4);
    split_bf16<<<nW4 / 256, 256>>>(wv, whi, wlo, nW4);
    gemm_tc<<<tgrid, 256>>>(ahi, alo, whi, wlo, bv, gV, NROWS, DD, DD);

    // Attention
    dim3 fgrid(SS / 128, HH, BB);        // (16, 16, 2)
    flash_attn<<<fgrid, 256, FLASH_SMEM_BYTES>>>(gQ, gK, gV, mask, gC);

    // Output projection
    split_bf16<<<nA4 / 256, 256>>>(gC, ahi, alo, nA4);
    split_bf16<<<nW4 / 256, 256>>>(wo, whi, wlo, nW4);
    gemm_tc<<<tgrid, 256>>>(ahi, alo, whi, wlo, bo, out, NROWS, DD, DD);
}

// round 8
// speedup vs baseline: 2.4581x; 1.7584x over previous
#include <cuda_runtime.h>
#include <cuda_bf16.h>
#include <math.h>
#include <stdint.h>

// Problem constants
#define BB   2
#define SS   2048
#define DD   1024
#define HH   16
#define DK   64
#define NROWS (BB*SS)   // 4096

typedef unsigned long long u64;

// Scratch (allocation-free rule: device globals) — all bf16 split pairs
__device__ __nv_bfloat16 g_Ahi[NROWS*DD];
__device__ __nv_bfloat16 g_Alo[NROWS*DD];
__device__ __nv_bfloat16 g_Whi[DD*DD];
__device__ __nv_bfloat16 g_Wlo[DD*DD];
__device__ __nv_bfloat16 g_Qhi[NROWS*DD];
__device__ __nv_bfloat16 g_Qlo[NROWS*DD];
__device__ __nv_bfloat16 g_Khi[NROWS*DD];
__device__ __nv_bfloat16 g_Klo[NROWS*DD];
__device__ __nv_bfloat16 g_Vhi[NROWS*DD];
__device__ __nv_bfloat16 g_Vlo[NROWS*DD];
__device__ __nv_bfloat16 g_Chi[NROWS*DD];
__device__ __nv_bfloat16 g_Clo[NROWS*DD];

// ---------------------------------------------------------------------------
// Base-ISA tensor helpers: ldmatrix + mma.sync (compile for plain sm_103)
// ---------------------------------------------------------------------------
__device__ __forceinline__ uint32_t smem_u32(const void* p) {
    uint32_t a;
    asm("{ .reg .u64 t; cvta.to.shared.u64 t, %1; cvt.u32.u64 %0, t; }" : "=r"(a) : "l"(p));
    return a;
}
__device__ __forceinline__ void ldsm_x4(uint32_t& r0, uint32_t& r1, uint32_t& r2,
                                        uint32_t& r3, uint32_t addr) {
    asm volatile("ldmatrix.sync.aligned.m8n8.x4.shared.b16 {%0,%1,%2,%3}, [%4];"
                 : "=r"(r0), "=r"(r1), "=r"(r2), "=r"(r3) : "r"(addr));
}
__device__ __forceinline__ void ldsm_x2(uint32_t& r0, uint32_t& r1, uint32_t addr) {
    asm volatile("ldmatrix.sync.aligned.m8n8.x2.shared.b16 {%0,%1}, [%2];"
                 : "=r"(r0), "=r"(r1) : "r"(addr));
}
__device__ __forceinline__ void ldsm_x2t(uint32_t& r0, uint32_t& r1, uint32_t addr) {
    asm volatile("ldmatrix.sync.aligned.m8n8.x2.trans.shared.b16 {%0,%1}, [%2];"
                 : "=r"(r0), "=r"(r1) : "r"(addr));
}
__device__ __forceinline__ void mma_bf16(float& c0, float& c1, float& c2, float& c3,
                                         uint32_t a0, uint32_t a1, uint32_t a2, uint32_t a3,
                                         uint32_t b0, uint32_t b1) {
    asm volatile("mma.sync.aligned.m16n8k16.row.col.f32.bf16.bf16.f32 "
                 "{%0,%1,%2,%3}, {%4,%5,%6,%7}, {%8,%9}, {%0,%1,%2,%3};"
                 : "+f"(c0), "+f"(c1), "+f"(c2), "+f"(c3)
                 : "r"(a0), "r"(a1), "r"(a2), "r"(a3), "r"(b0), "r"(b1));
}
// split a pair of fp32 into bf16x2 hi and bf16x2 lo (packed uint32)
__device__ __forceinline__ void split2(float a, float b, uint32_t& hi, uint32_t& lo) {
    __nv_bfloat162 h = __float22bfloat162_rn(make_float2(a, b));
    float2 hf = __bfloat1622float2(h);
    __nv_bfloat162 l = __float22bfloat162_rn(make_float2(a - hf.x, b - hf.y));
    hi = *(uint32_t*)&h;
    lo = *(uint32_t*)&l;
}

// ============================================================================
// fp32 -> (bf16 hi, bf16 lo) split (elementwise)
// ============================================================================
__global__ __launch_bounds__(256)
void split_bf16(const float* __restrict__ x, __nv_bfloat16* __restrict__ hi,
                __nv_bfloat16* __restrict__ lo, int n4)
{
    int i = blockIdx.x * blockDim.x + threadIdx.x;
    if (i >= n4) return;
    float4 v = ((const float4*)x)[i];
    uint2 hh, ll;
    split2(v.x, v.y, hh.x, ll.x);
    split2(v.z, v.w, hh.y, ll.y);
    ((uint2*)hi)[i] = hh;
    ((uint2*)lo)[i] = ll;
}

// ============================================================================
// Tensor-core GEMM via mma.sync bf16 split x3:
//   C[M,N] = A[M,K] * B[N,K]^T + bias[N]
// Block tile 128x128, K-chunk 32. 8 warps, warp tile 64x32.
// splitOut: 0 -> fp32 C; 1 -> bf16 hi/lo pair (Chi, Clo)
// ============================================================================
#define TBK 32
#define TROW 40   // smem row stride in bf16 (80B): conflict-free ldmatrix

__global__ __launch_bounds__(256)
void gemm_tc(const __nv_bfloat16* __restrict__ Ah, const __nv_bfloat16* __restrict__ Al,
             const __nv_bfloat16* __restrict__ Bh, const __nv_bfloat16* __restrict__ Bl,
             const float* __restrict__ bias, float* __restrict__ C,
             __nv_bfloat16* __restrict__ Chi, __nv_bfloat16* __restrict__ Clo,
             int M, int N, int K, int splitOut)
{
    __shared__ __nv_bfloat16 sAh[128 * TROW];
    __shared__ __nv_bfloat16 sAl[128 * TROW];
    __shared__ __nv_bfloat16 sBh[128 * TROW];
    __shared__ __nv_bfloat16 sBl[128 * TROW];

    const int t   = threadIdx.x;
    const int wid = t >> 5;
    const int lane = t & 31;
    const int m0 = blockIdx.y * 128;
    const int n0 = blockIdx.x * 128;
    const int wm = (wid & 1) * 64;
    const int wn = (wid >> 1) * 32;

    const uint32_t uAh = smem_u32(sAh);
    const uint32_t uAl = smem_u32(sAl);
    const uint32_t uBh = smem_u32(sBh);
    const uint32_t uBl = smem_u32(sBl);

    float acc[4][4][4];
#pragma unroll
    for (int i = 0; i < 4; i++)
#pragma unroll
        for (int j = 0; j < 4; j++)
#pragma unroll
            for (int r = 0; r < 4; r++) acc[i][j][r] = 0.f;

    for (int k0 = 0; k0 < K; k0 += TBK) {
        __syncthreads();
#pragma unroll
        for (int p = 0; p < 2; p++) {
            const int idx = t + p * 256;
            const int row = idx >> 2;
            const int c   = idx & 3;
            const size_t ga = (size_t)(m0 + row) * K + k0 + c * 8;
            const size_t gb = (size_t)(n0 + row) * K + k0 + c * 8;
            const int so = row * TROW + c * 8;
            *(uint4*)(sAh + so) = *(const uint4*)(Ah + ga);
            *(uint4*)(sAl + so) = *(const uint4*)(Al + ga);
            *(uint4*)(sBh + so) = *(const uint4*)(Bh + gb);
            *(uint4*)(sBl + so) = *(const uint4*)(Bl + gb);
        }
        __syncthreads();

#pragma unroll
        for (int ks = 0; ks < 2; ks++) {
            uint32_t ah[4][4], al[4][4];
#pragma unroll
            for (int ma = 0; ma < 4; ma++) {
                const int row = wm + ma * 16 + (lane & 15);
                const uint32_t off = (uint32_t)(row * TROW * 2 + ks * 32 + (lane >> 4) * 16);
                ldsm_x4(ah[ma][0], ah[ma][1], ah[ma][2], ah[ma][3], uAh + off);
                ldsm_x4(al[ma][0], al[ma][1], al[ma][2], al[ma][3], uAl + off);
            }
            uint32_t bh[4][2], bl[4][2];
#pragma unroll
            for (int na = 0; na < 4; na++) {
                const int row = wn + na * 8 + (lane & 7);
                const uint32_t off = (uint32_t)(row * TROW * 2 + ks * 32 + ((lane >> 3) & 1) * 16);
                ldsm_x2(bh[na][0], bh[na][1], uBh + off);
                ldsm_x2(bl[na][0], bl[na][1], uBl + off);
            }
#pragma unroll
            for (int ma = 0; ma < 4; ma++)
#pragma unroll
                for (int na = 0; na < 4; na++) {
                    float* c = acc[ma][na];
                    mma_bf16(c[0], c[1], c[2], c[3],
                             ah[ma][0], ah[ma][1], ah[ma][2], ah[ma][3],
                             bh[na][0], bh[na][1]);
                    mma_bf16(c[0], c[1], c[2], c[3],
                             ah[ma][0], ah[ma][1], ah[ma][2], ah[ma][3],
                             bl[na][0], bl[na][1]);
                    mma_bf16(c[0], c[1], c[2], c[3],
                             al[ma][0], al[ma][1], al[ma][2], al[ma][3],
                             bh[na][0], bh[na][1]);
                }
        }
    }

    const int g = lane >> 2;
    const int q = lane & 3;
#pragma unroll
    for (int ma = 0; ma < 4; ma++) {
#pragma unroll
        for (int na = 0; na < 4; na++) {
            const int col = n0 + wn + na * 8 + q * 2;
            const float b0 = bias[col], b1 = bias[col + 1];
            const int r0 = m0 + wm + ma * 16 + g;
            const float v00 = acc[ma][na][0] + b0, v01 = acc[ma][na][1] + b1;
            const float v10 = acc[ma][na][2] + b0, v11 = acc[ma][na][3] + b1;
            if (splitOut) {
                uint32_t h, l;
                split2(v00, v01, h, l);
                *(uint32_t*)(Chi + (size_t)r0 * N + col) = h;
                *(uint32_t*)(Clo + (size_t)r0 * N + col) = l;
                split2(v10, v11, h, l);
                *(uint32_t*)(Chi + (size_t)(r0 + 8) * N + col) = h;
                *(uint32_t*)(Clo + (size_t)(r0 + 8) * N + col) = l;
            } else {
                float* d0 = C + (size_t)r0 * N + col;
                d0[0] = v00; d0[1] = v01;
                float* d1 = C + (size_t)(r0 + 8) * N + col;
                d1[0] = v10; d1[1] = v11;
            }
        }
    }
}

// ============================================================================
// Flash attention on mma.sync (bf16 split x3 for both GEMMs).
// Block: 128 q-rows, 64-key tiles. 8 warps, warp = 16 rows x all 64 keys.
// Softmax fully warp-local. P stays in registers (C->A fragment identity).
// ============================================================================
#define FST 72                       // smem row stride in bf16 (144B)
#define FQ_OFF  0                    // Qhi: 128*FST | Qlo: 128*FST
#define FK_OFF  (2*128*FST)          // Khi/Klo: 64*FST each
#define FV_OFF  (FK_OFF + 2*64*FST)  // Vhi/Vlo: 64*FST each
#define F_BF16_TOTAL (FV_OFF + 2*64*FST)
#define FLASH_SMEM_BYTES (F_BF16_TOTAL*2 + 64*4)

__global__ __launch_bounds__(256, 2)
void flash_tc(const __nv_bfloat16* __restrict__ Qh, const __nv_bfloat16* __restrict__ Ql,
              const __nv_bfloat16* __restrict__ Kh, const __nv_bfloat16* __restrict__ Kl,
              const __nv_bfloat16* __restrict__ Vh, const __nv_bfloat16* __restrict__ Vl,
              const int* __restrict__ mask,
              __nv_bfloat16* __restrict__ Chi, __nv_bfloat16* __restrict__ Clo)
{
    extern __shared__ __nv_bfloat16 sb[];
    __nv_bfloat16* sQh = sb + FQ_OFF;
    __nv_bfloat16* sQl = sQh + 128 * FST;
    __nv_bfloat16* sKh = sb + FK_OFF;
    __nv_bfloat16* sKl = sKh + 64 * FST;
    __nv_bfloat16* sVh = sb + FV_OFF;
    __nv_bfloat16* sVl = sVh + 64 * FST;
    int* ms = (int*)(sb + F_BF16_TOTAL);

    const int t    = threadIdx.x;
    const int wid  = t >> 5;
    const int lane = t & 31;
    const int g    = lane >> 2;
    const int q    = lane & 3;
    const int i0   = blockIdx.x * 128;
    const int h    = blockIdx.y;
    const int b    = blockIdx.z;
    const size_t base = (size_t)b * SS * DD + (size_t)h * DK;

    const uint32_t uQh = smem_u32(sQh);
    const uint32_t uQl = smem_u32(sQl);
    const uint32_t uKh = smem_u32(sKh);
    const uint32_t uKl = smem_u32(sKl);
    const uint32_t uVh = smem_u32(sVh);
    const uint32_t uVl = smem_u32(sVl);

    // Load Q tile (128 rows x 64 dk, hi+lo)
#pragma unroll
    for (int p = 0; p < 4; p++) {
        const int idx = t + p * 256;
        const int row = idx >> 3;
        const int c   = (idx & 7) * 8;
        const size_t ga = base + (size_t)(i0 + row) * DD + c;
        *(uint4*)(sQh + row * FST + c) = *(const uint4*)(Qh + ga);
        *(uint4*)(sQl + row * FST + c) = *(const uint4*)(Ql + ga);
    }

    float o[8][4];
#pragma unroll
    for (int na = 0; na < 8; na++)
#pragma unroll
        for (int r = 0; r < 4; r++) o[na][r] = 0.f;
    float m0 = -INFINITY, m1 = -INFINITY, l0 = 0.f, l1 = 0.f;
    const float scale = 0.125f;  // 1/sqrt(64)

    for (int j0 = 0; j0 < SS; j0 += 64) {
        __syncthreads();
        // Load K, V tiles (64 rows x 64 dk, hi+lo)
#pragma unroll
        for (int p = 0; p < 2; p++) {
            const int idx = t + p * 256;
            const int row = idx >> 3;
            const int c   = (idx & 7) * 8;
            const size_t gk = base + (size_t)(j0 + row) * DD + c;
            *(uint4*)(sKh + row * FST + c) = *(const uint4*)(Kh + gk);
            *(uint4*)(sKl + row * FST + c) = *(const uint4*)(Kl + gk);
            *(uint4*)(sVh + row * FST + c) = *(const uint4*)(Vh + gk);
            *(uint4*)(sVl + row * FST + c) = *(const uint4*)(Vl + gk);
        }
        if (t < 64) ms[t] = mask[b * SS + j0 + t];
        __syncthreads();

        // ---- GEMM1: S[16 rows x 64 keys] per warp ----
        float s[8][4];
#pragma unroll
        for (int na = 0; na < 8; na++)
#pragma unroll
            for (int r = 0; r < 4; r++) s[na][r] = 0.f;

#pragma unroll
        for (int ks = 0; ks < 4; ks++) {
            uint32_t ah[4], al[4];
            const uint32_t aoff = (uint32_t)((wid * 16 + (lane & 15)) * 144 + ks * 32 + (lane >> 4) * 16);
            ldsm_x4(ah[0], ah[1], ah[2], ah[3], uQh + aoff);
            ldsm_x4(al[0], al[1], al[2], al[3], uQl + aoff);
#pragma unroll
            for (int na = 0; na < 8; na++) {
                const uint32_t boff = (uint32_t)((na * 8 + (lane & 7)) * 144 + ks * 32 + ((lane >> 3) & 1) * 16);
                uint32_t bh0, bh1, bl0, bl1;
                ldsm_x2(bh0, bh1, uKh + boff);
                ldsm_x2(bl0, bl1, uKl + boff);
                mma_bf16(s[na][0], s[na][1], s[na][2], s[na][3],
                         ah[0], ah[1], ah[2], ah[3], bh0, bh1);
                mma_bf16(s[na][0], s[na][1], s[na][2], s[na][3],
                         ah[0], ah[1], ah[2], ah[3], bl0, bl1);
                mma_bf16(s[na][0], s[na][1], s[na][2], s[na][3],
                         al[0], al[1], al[2], al[3], bh0, bh1);
            }
        }

        // ---- scale + mask ----
#pragma unroll
        for (int na = 0; na < 8; na++) {
            const int kc = na * 8 + q * 2;
            const int mk0 = ms[kc], mk1 = ms[kc + 1];
            s[na][0] = mk0 ? s[na][0] * scale : -1e9f;
            s[na][1] = mk1 ? s[na][1] * scale : -1e9f;
            s[na][2] = mk0 ? s[na][2] * scale : -1e9f;
            s[na][3] = mk1 ? s[na][3] * scale : -1e9f;
        }

        // ---- online softmax (rows g and g+8; 4 lanes per row) ----
        float mx0 = -INFINITY, mx1 = -INFINITY;
#pragma unroll
        for (int na = 0; na < 8; na++) {
            mx0 = fmaxf(mx0, fmaxf(s[na][0], s[na][1]));
            mx1 = fmaxf(mx1, fmaxf(s[na][2], s[na][3]));
        }
        mx0 = fmaxf(mx0, __shfl_xor_sync(0xffffffffu, mx0, 1));
        mx0 = fmaxf(mx0, __shfl_xor_sync(0xffffffffu, mx0, 2));
        mx1 = fmaxf(mx1, __shfl_xor_sync(0xffffffffu, mx1, 1));
        mx1 = fmaxf(mx1, __shfl_xor_sync(0xffffffffu, mx1, 2));
        const float mn0 = fmaxf(m0, mx0), mn1 = fmaxf(m1, mx1);
        const float a0 = __expf(m0 - mn0), a1 = __expf(m1 - mn1);
        float sum0 = 0.f, sum1 = 0.f;
#pragma unroll
        for (int na = 0; na < 8; na++) {
            s[na][0] = __expf(s[na][0] - mn0); sum0 += s[na][0];
            s[na][1] = __expf(s[na][1] - mn0); sum0 += s[na][1];
            s[na][2] = __expf(s[na][2] - mn1); sum1 += s[na][2];
            s[na][3] = __expf(s[na][3] - mn1); sum1 += s[na][3];
        }
        sum0 += __shfl_xor_sync(0xffffffffu, sum0, 1);
        sum0 += __shfl_xor_sync(0xffffffffu, sum0, 2);
        sum1 += __shfl_xor_sync(0xffffffffu, sum1, 1);
        sum1 += __shfl_xor_sync(0xffffffffu, sum1, 2);
        l0 = l0 * a0 + sum0;
        l1 = l1 * a1 + sum1;
        m0 = mn0; m1 = mn1;
#pragma unroll
        for (int na = 0; na < 8; na++) {
            o[na][0] *= a0; o[na][1] *= a0;
            o[na][2] *= a1; o[na][3] *= a1;
        }

        // ---- GEMM2: O += P * V  (P in registers, V via ldmatrix.trans) ----
#pragma unroll
        for (int kk = 0; kk < 4; kk++) {
            uint32_t ph[4], pl[4];
            split2(s[2*kk][0],     s[2*kk][1],     ph[0], pl[0]);
            split2(s[2*kk][2],     s[2*kk][3],     ph[1], pl[1]);
            split2(s[2*kk+1][0],   s[2*kk+1][1],   ph[2], pl[2]);
            split2(s[2*kk+1][2],   s[2*kk+1][3],   ph[3], pl[3]);
            const uint32_t vrow = (uint32_t)((kk * 16 + (lane & 15)) * 144);
#pragma unroll
            for (int na = 0; na < 8; na++) {
                uint32_t vh0, vh1, vl0, vl1;
                ldsm_x2t(vh0, vh1, uVh + vrow + na * 16);
                ldsm_x2t(vl0, vl1, uVl + vrow + na * 16);
                mma_bf16(o[na][0], o[na][1], o[na][2], o[na][3],
                         ph[0], ph[1], ph[2], ph[3], vh0, vh1);
                mma_bf16(o[na][0], o[na][1], o[na][2], o[na][3],
                         ph[0], ph[1], ph[2], ph[3], vl0, vl1);
                mma_bf16(o[na][0], o[na][1], o[na][2], o[na][3],
                         pl[0], pl[1], pl[2], pl[3], vh0, vh1);
            }
        }
    }

    // ---- epilogue: divide by l, write split bf16 context ----
    const float inv0 = 1.f / l0, inv1 = 1.f / l1;
    const int r0 = i0 + wid * 16 + g;
#pragma unroll
    for (int na = 0; na < 8; na++) {
        const int col = na * 8 + q * 2;
        const size_t p0 = base + (size_t)r0 * DD + col;
        const size_t p1 = base + (size_t)(r0 + 8) * DD + col;
        uint32_t hh, ll;
        split2(o[na][0] * inv0, o[na][1] * inv0, hh, ll);
        *(uint32_t*)(Chi + p0) = hh;
        *(uint32_t*)(Clo + p0) = ll;
        split2(o[na][2] * inv1, o[na][3] * inv1, hh, ll);
        *(uint32_t*)(Chi + p1) = hh;
        *(uint32_t*)(Clo + p1) = ll;
    }
}

// ============================================================================
// kernel_launch
// ============================================================================
extern "C" void kernel_launch(void* const* d_in, const int* in_sizes, int n_in,
                              void* d_out, int out_size)
{
    const float* q    = (const float*)d_in[0];
    const float* k    = (const float*)d_in[1];
    const float* v    = (const float*)d_in[2];
    const int*   mask = (const int*)  d_in[3];
    const float* wq   = (const float*)d_in[4];
    const float* bq   = (const float*)d_in[5];
    const float* wk   = (const float*)d_in[6];
    const float* bk   = (const float*)d_in[7];
    const float* wv   = (const float*)d_in[8];
    const float* bv   = (const float*)d_in[9];
    const float* wo   = (const float*)d_in[10];
    const float* bo   = (const float*)d_in[11];
    float* out = (float*)d_out;

    __nv_bfloat16 *ahi, *alo, *whi, *wlo;
    __nv_bfloat16 *qhi, *qlo, *khi, *klo, *vhi, *vlo, *chi, *clo;
    cudaGetSymbolAddress((void**)&ahi, g_Ahi);
    cudaGetSymbolAddress((void**)&alo, g_Alo);
    cudaGetSymbolAddress((void**)&whi, g_Whi);
    cudaGetSymbolAddress((void**)&wlo, g_Wlo);
    cudaGetSymbolAddress((void**)&qhi, g_Qhi);
    cudaGetSymbolAddress((void**)&qlo, g_Qlo);
    cudaGetSymbolAddress((void**)&khi, g_Khi);
    cudaGetSymbolAddress((void**)&klo, g_Klo);
    cudaGetSymbolAddress((void**)&vhi, g_Vhi);
    cudaGetSymbolAddress((void**)&vlo, g_Vlo);
    cudaGetSymbolAddress((void**)&chi, g_Chi);
    cudaGetSymbolAddress((void**)&clo, g_Clo);

    static bool attr_set = false;
    if (!attr_set) {
        cudaFuncSetAttribute(flash_tc, cudaFuncAttributeMaxDynamicSharedMemorySize,
                             FLASH_SMEM_BYTES);
        attr_set = true;
    }

    const int nA4 = NROWS * DD / 4;
    const int nW4 = DD * DD / 4;
    dim3 tgrid(DD / 128, NROWS / 128);   // (8, 32)

    // Q projection -> split bf16
    split_bf16<<<nA4 / 256, 256>>>(q, ahi, alo, nA4);
    split_bf16<<<nW4 / 256, 256>>>(wq, whi, wlo, nW4);
    gemm_tc<<<tgrid, 256>>>(ahi, alo, whi, wlo, bq, nullptr, qhi, qlo, NROWS, DD, DD, 1);
    // K projection
    split_bf16<<<nA4 / 256, 256>>>(k, ahi, alo, nA4);
    split_bf16<<<nW4 / 256, 256>>>(wk, whi, wlo, nW4);
    gemm_tc<<<tgrid, 256>>>(ahi, alo, whi, wlo, bk, nullptr, khi, klo, NROWS, DD, DD, 1);
    // V projection
    split_bf16<<<nA4 / 256, 256>>>(v, ahi, alo, nA4);
    split_bf16<<<nW4 / 256, 256>>>(wv, whi, wlo, nW4);
    gemm_tc<<<tgrid, 256>>>(ahi, alo, whi, wlo, bv, nullptr, vhi, vlo, NROWS, DD, DD, 1);

    // Attention (writes split bf16 context directly)
    dim3 fgrid(SS / 128, HH, BB);        // (16, 16, 2)
    flash_tc<<<fgrid, 256, FLASH_SMEM_BYTES>>>(qhi, qlo, khi, klo, vhi, vlo, mask, chi, clo);

    // Output projection (fp32 out)
    split_bf16<<<nW4 / 256, 256>>>(wo, whi, wlo, nW4);
    gemm_tc<<<tgrid, 256>>>(chi, clo, whi, wlo, bo, out, nullptr, nullptr, NROWS, DD, DD, 0);
}

// round 9
// speedup vs baseline: 2.7615x; 1.1234x over previous
#include <cuda_runtime.h>
#include <cuda_bf16.h>
#include <math.h>
#include <stdint.h>

// Problem constants
#define BB   2
#define SS   2048
#define DD   1024
#define HH   16
#define DK   64
#define NROWS (BB*SS)   // 4096

typedef unsigned long long u64;

// Scratch (allocation-free rule: device globals) — all bf16 split pairs
__device__ __nv_bfloat16 g_Ahi[NROWS*DD];
__device__ __nv_bfloat16 g_Alo[NROWS*DD];
__device__ __nv_bfloat16 g_Whi[DD*DD];
__device__ __nv_bfloat16 g_Wlo[DD*DD];
__device__ __nv_bfloat16 g_Qhi[NROWS*DD];
__device__ __nv_bfloat16 g_Qlo[NROWS*DD];
__device__ __nv_bfloat16 g_Khi[NROWS*DD];
__device__ __nv_bfloat16 g_Klo[NROWS*DD];
__device__ __nv_bfloat16 g_Vhi[NROWS*DD];
__device__ __nv_bfloat16 g_Vlo[NROWS*DD];
__device__ __nv_bfloat16 g_Chi[NROWS*DD];
__device__ __nv_bfloat16 g_Clo[NROWS*DD];

// ---------------------------------------------------------------------------
// Base-ISA helpers: ldmatrix + mma.sync + cp.async (all compile for sm_103)
// ---------------------------------------------------------------------------
__device__ __forceinline__ uint32_t smem_u32(const void* p) {
    uint32_t a;
    asm("{ .reg .u64 t; cvta.to.shared.u64 t, %1; cvt.u32.u64 %0, t; }" : "=r"(a) : "l"(p));
    return a;
}
__device__ __forceinline__ void ldsm_x4(uint32_t& r0, uint32_t& r1, uint32_t& r2,
                                        uint32_t& r3, uint32_t addr) {
    asm volatile("ldmatrix.sync.aligned.m8n8.x4.shared.b16 {%0,%1,%2,%3}, [%4];"
                 : "=r"(r0), "=r"(r1), "=r"(r2), "=r"(r3) : "r"(addr));
}
__device__ __forceinline__ void ldsm_x4t(uint32_t& r0, uint32_t& r1, uint32_t& r2,
                                         uint32_t& r3, uint32_t addr) {
    asm volatile("ldmatrix.sync.aligned.m8n8.x4.trans.shared.b16 {%0,%1,%2,%3}, [%4];"
                 : "=r"(r0), "=r"(r1), "=r"(r2), "=r"(r3) : "r"(addr));
}
__device__ __forceinline__ void mma_bf16(float& c0, float& c1, float& c2, float& c3,
                                         uint32_t a0, uint32_t a1, uint32_t a2, uint32_t a3,
                                         uint32_t b0, uint32_t b1) {
    asm volatile("mma.sync.aligned.m16n8k16.row.col.f32.bf16.bf16.f32 "
                 "{%0,%1,%2,%3}, {%4,%5,%6,%7}, {%8,%9}, {%0,%1,%2,%3};"
                 : "+f"(c0), "+f"(c1), "+f"(c2), "+f"(c3)
                 : "r"(a0), "r"(a1), "r"(a2), "r"(a3), "r"(b0), "r"(b1));
}
__device__ __forceinline__ void cp16(uint32_t saddr, const void* g) {
    asm volatile("cp.async.cg.shared.global [%0], [%1], 16;" :: "r"(saddr), "l"(g));
}
#define CP_COMMIT() asm volatile("cp.async.commit_group;" ::: "memory")
#define CP_WAIT0()  asm volatile("cp.async.wait_group 0;"  ::: "memory")

// split a pair of fp32 into bf16x2 hi and bf16x2 lo (packed uint32)
__device__ __forceinline__ void split2(float a, float b, uint32_t& hi, uint32_t& lo) {
    __nv_bfloat162 h = __float22bfloat162_rn(make_float2(a, b));
    float2 hf = __bfloat1622float2(h);
    __nv_bfloat162 l = __float22bfloat162_rn(make_float2(a - hf.x, b - hf.y));
    hi = *(uint32_t*)&h;
    lo = *(uint32_t*)&l;
}

// ============================================================================
// fp32 -> (bf16 hi, bf16 lo) split (elementwise)
// ============================================================================
__global__ __launch_bounds__(256)
void split_bf16(const float* __restrict__ x, __nv_bfloat16* __restrict__ hi,
                __nv_bfloat16* __restrict__ lo, int n4)
{
    int i = blockIdx.x * blockDim.x + threadIdx.x;
    if (i >= n4) return;
    float4 v = ((const float4*)x)[i];
    uint2 hh, ll;
    split2(v.x, v.y, hh.x, ll.x);
    split2(v.z, v.w, hh.y, ll.y);
    ((uint2*)hi)[i] = hh;
    ((uint2*)lo)[i] = ll;
}

// ============================================================================
// Tensor-core GEMM, cp.async 2-stage pipelined, bf16 split x3:
//   C[M,N] = A[M,K] * W[N,K]^T + bias[N]
// Block tile 128x128, K-chunk 32. 8 warps, warp tile 64x32.
// ============================================================================
#define TBK 32
#define TROW 40                  // smem row stride (bf16): 80B, conflict-free ldmatrix
#define GTILEB (128*TROW*2)      // bytes per tile array
#define GS_TOTAL (2*4*GTILEB)    // 2 stages x 4 arrays = 81920 B

__global__ __launch_bounds__(256)
void gemm_tc(const __nv_bfloat16* __restrict__ Ah, const __nv_bfloat16* __restrict__ Al,
             const __nv_bfloat16* __restrict__ Bh, const __nv_bfloat16* __restrict__ Bl,
             const float* __restrict__ bias, float* __restrict__ C,
             __nv_bfloat16* __restrict__ Chi, __nv_bfloat16* __restrict__ Clo,
             int M, int N, int K, int splitOut)
{
    extern __shared__ char dynsm[];
    const uint32_t uS = smem_u32(dynsm);

    const int t    = threadIdx.x;
    const int wid  = t >> 5;
    const int lane = t & 31;
    const int m0 = blockIdx.y * 128;
    const int n0 = blockIdx.x * 128;
    const int wm = (wid & 1) * 64;
    const int wn = (wid >> 1) * 32;
    const int nchunk = K / TBK;

    // load indexing (per thread, 2 passes per array)
    const int lrow0 = t >> 2;            // 0..63
    const int lcc   = (t & 3) * 8;       // bf16 col: 0,8,16,24

#define G_ISSUE(c, s) do {                                                     \
        const int _k0 = (c) * TBK;                                             \
        _Pragma("unroll")                                                      \
        for (int _p = 0; _p < 2; _p++) {                                       \
            const int _row = lrow0 + _p * 64;                                  \
            const uint32_t _so = (uint32_t)((_row * TROW + lcc) * 2);          \
            const size_t _ga = (size_t)(m0 + _row) * K + _k0 + lcc;            \
            const size_t _gb = (size_t)(n0 + _row) * K + _k0 + lcc;            \
            const uint32_t _b = uS + (uint32_t)((s) * 4) * GTILEB;             \
            cp16(_b + 0 * GTILEB + _so, Ah + _ga);                             \
            cp16(_b + 1 * GTILEB + _so, Al + _ga);                             \
            cp16(_b + 2 * GTILEB + _so, Bh + _gb);                             \
            cp16(_b + 3 * GTILEB + _so, Bl + _gb);                             \
        }                                                                      \
        CP_COMMIT();                                                           \
    } while (0)

    float acc[4][4][4];
#pragma unroll
    for (int i = 0; i < 4; i++)
#pragma unroll
        for (int j = 0; j < 4; j++)
#pragma unroll
            for (int r = 0; r < 4; r++) acc[i][j][r] = 0.f;

    G_ISSUE(0, 0);

    for (int c = 0; c < nchunk; c++) {
        const int s = c & 1;
        CP_WAIT0();
        __syncthreads();
        if (c + 1 < nchunk) G_ISSUE(c + 1, 1 - s);

        const uint32_t uAh = uS + (uint32_t)(s * 4 + 0) * GTILEB;
        const uint32_t uAl = uS + (uint32_t)(s * 4 + 1) * GTILEB;
        const uint32_t uBh = uS + (uint32_t)(s * 4 + 2) * GTILEB;
        const uint32_t uBl = uS + (uint32_t)(s * 4 + 3) * GTILEB;

#pragma unroll
        for (int ks = 0; ks < 2; ks++) {
            uint32_t ah[4][4], al[4][4];
#pragma unroll
            for (int ma = 0; ma < 4; ma++) {
                const int row = wm + ma * 16 + (lane & 15);
                const uint32_t off = (uint32_t)(row * TROW * 2 + ks * 32 + (lane >> 4) * 16);
                ldsm_x4(ah[ma][0], ah[ma][1], ah[ma][2], ah[ma][3], uAh + off);
                ldsm_x4(al[ma][0], al[ma][1], al[ma][2], al[ma][3], uAl + off);
            }
            // B fragments: x4 merge, 2 na per ldmatrix
            uint32_t bh[4][2], bl[4][2];
#pragma unroll
            for (int np = 0; np < 2; np++) {
                const int m = lane >> 3;
                const int row = wn + np * 16 + (m >> 1) * 8 + (lane & 7);
                const uint32_t off = (uint32_t)(row * TROW * 2 + ks * 32 + (m & 1) * 16);
                ldsm_x4(bh[np*2][0], bh[np*2][1], bh[np*2+1][0], bh[np*2+1][1], uBh + off);
                ldsm_x4(bl[np*2][0], bl[np*2][1], bl[np*2+1][0], bl[np*2+1][1], uBl + off);
            }
#pragma unroll
            for (int ma = 0; ma < 4; ma++)
#pragma unroll
                for (int na = 0; na < 4; na++) {
                    float* cc = acc[ma][na];
                    mma_bf16(cc[0], cc[1], cc[2], cc[3],
                             ah[ma][0], ah[ma][1], ah[ma][2], ah[ma][3],
                             bh[na][0], bh[na][1]);
                    mma_bf16(cc[0], cc[1], cc[2], cc[3],
                             ah[ma][0], ah[ma][1], ah[ma][2], ah[ma][3],
                             bl[na][0], bl[na][1]);
                    mma_bf16(cc[0], cc[1], cc[2], cc[3],
                             al[ma][0], al[ma][1], al[ma][2], al[ma][3],
                             bh[na][0], bh[na][1]);
                }
        }
        __syncthreads();
    }

    const int g = lane >> 2;
    const int q = lane & 3;
#pragma unroll
    for (int ma = 0; ma < 4; ma++) {
#pragma unroll
        for (int na = 0; na < 4; na++) {
            const int col = n0 + wn + na * 8 + q * 2;
            const float b0 = bias[col], b1 = bias[col + 1];
            const int r0 = m0 + wm + ma * 16 + g;
            const float v00 = acc[ma][na][0] + b0, v01 = acc[ma][na][1] + b1;
            const float v10 = acc[ma][na][2] + b0, v11 = acc[ma][na][3] + b1;
            if (splitOut) {
                uint32_t h, l;
                split2(v00, v01, h, l);
                *(uint32_t*)(Chi + (size_t)r0 * N + col) = h;
                *(uint32_t*)(Clo + (size_t)r0 * N + col) = l;
                split2(v10, v11, h, l);
                *(uint32_t*)(Chi + (size_t)(r0 + 8) * N + col) = h;
                *(uint32_t*)(Clo + (size_t)(r0 + 8) * N + col) = l;
            } else {
                float* d0 = C + (size_t)r0 * N + col;
                d0[0] = v00; d0[1] = v01;
                float* d1 = C + (size_t)(r0 + 8) * N + col;
                d1[0] = v10; d1[1] = v11;
            }
        }
    }
}

// ============================================================================
// Flash attention on mma.sync, cp.async double-buffered K/V, x4 ldmatrix.
// Block: 128 q-rows, 64-key tiles. 8 warps = 16 rows x all 64 keys each.
// One __syncthreads per key tile. P stays in registers.
// ============================================================================
#define FST 72                        // smem row stride (bf16): 144 B
#define FSTB (FST*2)
#define QTILEB (128*FSTB)             // 36864 B per Q array
#define KTILEB (64*FSTB)              // 18432 B per K/V array per stage
#define FKV (2*QTILEB)
#define FMS (FKV + 8*KTILEB)          // int ms[2][64]
#define FLASH_SMEM_BYTES (FMS + 512)  // 111104 B

__global__ __launch_bounds__(256, 2)
void flash_tc(const __nv_bfloat16* __restrict__ Qh, const __nv_bfloat16* __restrict__ Ql,
              const __nv_bfloat16* __restrict__ Kh, const __nv_bfloat16* __restrict__ Kl,
              const __nv_bfloat16* __restrict__ Vh, const __nv_bfloat16* __restrict__ Vl,
              const int* __restrict__ mask,
              __nv_bfloat16* __restrict__ Chi, __nv_bfloat16* __restrict__ Clo)
{
    extern __shared__ char dynsm[];
    const uint32_t uS = smem_u32(dynsm);
    const uint32_t uQh = uS, uQl = uS + QTILEB;
    int* ms = (int*)(dynsm + FMS);

    const int t    = threadIdx.x;
    const int wid  = t >> 5;
    const int lane = t & 31;
    const int g    = lane >> 2;
    const int q    = lane & 3;
    const int i0   = blockIdx.x * 128;
    const int h    = blockIdx.y;
    const int b    = blockIdx.z;
    const size_t base = (size_t)b * SS * DD + (size_t)h * DK;

    // Load Q tile (plain stores; first loop-top sync publishes them)
    {
        __nv_bfloat16* sQh = (__nv_bfloat16*)dynsm;
        __nv_bfloat16* sQl = sQh + 128 * FST;
#pragma unroll
        for (int p = 0; p < 4; p++) {
            const int idx = t + p * 256;
            const int row = idx >> 3;
            const int c   = (idx & 7) * 8;
            const size_t ga = base + (size_t)(i0 + row) * DD + c;
            *(uint4*)(sQh + row * FST + c) = *(const uint4*)(Qh + ga);
            *(uint4*)(sQl + row * FST + c) = *(const uint4*)(Ql + ga);
        }
    }

    const int lrow = t >> 3;         // 0..31
    const int lcc  = (t & 7) * 8;    // bf16 col

#define F_ISSUE(jt, s) do {                                                    \
        const int _j0 = (jt) * 64;                                             \
        _Pragma("unroll")                                                      \
        for (int _p = 0; _p < 2; _p++) {                                       \
            const int _row = lrow + _p * 32;                                   \
            const size_t _gk = base + (size_t)(_j0 + _row) * DD + lcc;         \
            const uint32_t _so = (uint32_t)(_row * FSTB + lcc * 2);            \
            cp16(uS + FKV + (uint32_t)(0 * 2 + (s)) * KTILEB + _so, Kh + _gk); \
            cp16(uS + FKV + (uint32_t)(1 * 2 + (s)) * KTILEB + _so, Kl + _gk); \
            cp16(uS + FKV + (uint32_t)(2 * 2 + (s)) * KTILEB + _so, Vh + _gk); \
            cp16(uS + FKV + (uint32_t)(3 * 2 + (s)) * KTILEB + _so, Vl + _gk); \
        }                                                                      \
        if (t < 16)                                                            \
            asm volatile("cp.async.ca.shared.global [%0], [%1], 16;"           \
                :: "r"(uS + FMS + (uint32_t)(s) * 256 + (uint32_t)t * 16),     \
                   "l"(mask + (size_t)b * SS + _j0 + t * 4));                  \
        CP_COMMIT();                                                           \
    } while (0)

    float o[8][4];
#pragma unroll
    for (int na = 0; na < 8; na++)
#pragma unroll
        for (int r = 0; r < 4; r++) o[na][r] = 0.f;
    float m0 = -INFINITY, m1 = -INFINITY, l0 = 0.f, l1 = 0.f;
    const float scale = 0.125f;  // 1/sqrt(64)

    F_ISSUE(0, 0);

    for (int jt = 0; jt < SS / 64; jt++) {
        const int s = jt & 1;
        CP_WAIT0();
        __syncthreads();   // KV[jt]+mask visible; all warps done with stage 1-s
        if (jt + 1 < SS / 64) F_ISSUE(jt + 1, 1 - s);

        const uint32_t uKh = uS + FKV + (uint32_t)(0 * 2 + s) * KTILEB;
        const uint32_t uKl = uS + FKV + (uint32_t)(1 * 2 + s) * KTILEB;
        const uint32_t uVh = uS + FKV + (uint32_t)(2 * 2 + s) * KTILEB;
        const uint32_t uVl = uS + FKV + (uint32_t)(3 * 2 + s) * KTILEB;
        const int* msj = ms + s * 64;

        // ---- GEMM1: S[16 rows x 64 keys] per warp ----
        float sc[8][4];
#pragma unroll
        for (int na = 0; na < 8; na++)
#pragma unroll
            for (int r = 0; r < 4; r++) sc[na][r] = 0.f;

#pragma unroll
        for (int ks = 0; ks < 4; ks++) {
            uint32_t ah[4], al[4];
            const uint32_t aoff = (uint32_t)((wid * 16 + (lane & 15)) * FSTB
                                             + ks * 32 + (lane >> 4) * 16);
            ldsm_x4(ah[0], ah[1], ah[2], ah[3], uQh + aoff);
            ldsm_x4(al[0], al[1], al[2], al[3], uQl + aoff);
#pragma unroll
            for (int np = 0; np < 4; np++) {
                const int m = lane >> 3;
                const int row = np * 16 + (m >> 1) * 8 + (lane & 7);
                const uint32_t boff = (uint32_t)(row * FSTB + ks * 32 + (m & 1) * 16);
                uint32_t b0h, b1h, b2h, b3h, b0l, b1l, b2l, b3l;
                ldsm_x4(b0h, b1h, b2h, b3h, uKh + boff);
                ldsm_x4(b0l, b1l, b2l, b3l, uKl + boff);
                const int na0 = np * 2, na1 = np * 2 + 1;
                mma_bf16(sc[na0][0], sc[na0][1], sc[na0][2], sc[na0][3],
                         ah[0], ah[1], ah[2], ah[3], b0h, b1h);
                mma_bf16(sc[na0][0], sc[na0][1], sc[na0][2], sc[na0][3],
                         ah[0], ah[1], ah[2], ah[3], b0l, b1l);
                mma_bf16(sc[na0][0], sc[na0][1], sc[na0][2], sc[na0][3],
                         al[0], al[1], al[2], al[3], b0h, b1h);
                mma_bf16(sc[na1][0], sc[na1][1], sc[na1][2], sc[na1][3],
                         ah[0], ah[1], ah[2], ah[3], b2h, b3h);
                mma_bf16(sc[na1][0], sc[na1][1], sc[na1][2], sc[na1][3],
                         ah[0], ah[1], ah[2], ah[3], b2l, b3l);
                mma_bf16(sc[na1][0], sc[na1][1], sc[na1][2], sc[na1][3],
                         al[0], al[1], al[2], al[3], b2h, b3h);
            }
        }

        // ---- scale + mask ----
#pragma unroll
        for (int na = 0; na < 8; na++) {
            const int kc = na * 8 + q * 2;
            const int mk0 = msj[kc], mk1 = msj[kc + 1];
            sc[na][0] = mk0 ? sc[na][0] * scale : -1e9f;
            sc[na][1] = mk1 ? sc[na][1] * scale : -1e9f;
            sc[na][2] = mk0 ? sc[na][2] * scale : -1e9f;
            sc[na][3] = mk1 ? sc[na][3] * scale : -1e9f;
        }

        // ---- online softmax (rows g and g+8; 4 lanes per row) ----
        float mx0 = -INFINITY, mx1 = -INFINITY;
#pragma unroll
        for (int na = 0; na < 8; na++) {
            mx0 = fmaxf(mx0, fmaxf(sc[na][0], sc[na][1]));
            mx1 = fmaxf(mx1, fmaxf(sc[na][2], sc[na][3]));
        }
        mx0 = fmaxf(mx0, __shfl_xor_sync(0xffffffffu, mx0, 1));
        mx0 = fmaxf(mx0, __shfl_xor_sync(0xffffffffu, mx0, 2));
        mx1 = fmaxf(mx1, __shfl_xor_sync(0xffffffffu, mx1, 1));
        mx1 = fmaxf(mx1, __shfl_xor_sync(0xffffffffu, mx1, 2));
        const float mn0 = fmaxf(m0, mx0), mn1 = fmaxf(m1, mx1);
        const float a0 = __expf(m0 - mn0), a1 = __expf(m1 - mn1);
        float sum0 = 0.f, sum1 = 0.f;
#pragma unroll
        for (int na = 0; na < 8; na++) {
            sc[na][0] = __expf(sc[na][0] - mn0); sum0 += sc[na][0];
            sc[na][1] = __expf(sc[na][1] - mn0); sum0 += sc[na][1];
            sc[na][2] = __expf(sc[na][2] - mn1); sum1 += sc[na][2];
            sc[na][3] = __expf(sc[na][3] - mn1); sum1 += sc[na][3];
        }
        sum0 += __shfl_xor_sync(0xffffffffu, sum0, 1);
        sum0 += __shfl_xor_sync(0xffffffffu, sum0, 2);
        sum1 += __shfl_xor_sync(0xffffffffu, sum1, 1);
        sum1 += __shfl_xor_sync(0xffffffffu, sum1, 2);
        l0 = l0 * a0 + sum0;
        l1 = l1 * a1 + sum1;
        m0 = mn0; m1 = mn1;
#pragma unroll
        for (int na = 0; na < 8; na++) {
            o[na][0] *= a0; o[na][1] *= a0;
            o[na][2] *= a1; o[na][3] *= a1;
        }

        // ---- GEMM2: O += P * V  (P in registers, V via ldmatrix.x4.trans) ----
#pragma unroll
        for (int kk = 0; kk < 4; kk++) {
            uint32_t ph[4], pl[4];
            split2(sc[2*kk][0],   sc[2*kk][1],   ph[0], pl[0]);
            split2(sc[2*kk][2],   sc[2*kk][3],   ph[1], pl[1]);
            split2(sc[2*kk+1][0], sc[2*kk+1][1], ph[2], pl[2]);
            split2(sc[2*kk+1][2], sc[2*kk+1][3], ph[3], pl[3]);
            const int m = lane >> 3;
#pragma unroll
            for (int np = 0; np < 4; np++) {
                // x4 trans: matrices (na0,kr0)(na0,kr1)(na1,kr0)(na1,kr1)
                const int row = kk * 16 + (m & 1) * 8 + (lane & 7);
                const int na0 = np * 2, na1 = np * 2 + 1;
                const uint32_t voff = (uint32_t)(row * FSTB + (np * 2 + (m >> 1)) * 16);
                uint32_t v0h, v1h, v2h, v3h, v0l, v1l, v2l, v3l;
                ldsm_x4t(v0h, v1h, v2h, v3h, uVh + voff);
                ldsm_x4t(v0l, v1l, v2l, v3l, uVl + voff);
                mma_bf16(o[na0][0], o[na0][1], o[na0][2], o[na0][3],
                         ph[0], ph[1], ph[2], ph[3], v0h, v1h);
                mma_bf16(o[na0][0], o[na0][1], o[na0][2], o[na0][3],
                         ph[0], ph[1], ph[2], ph[3], v0l, v1l);
                mma_bf16(o[na0][0], o[na0][1], o[na0][2], o[na0][3],
                         pl[0], pl[1], pl[2], pl[3], v0h, v1h);
                mma_bf16(o[na1][0], o[na1][1], o[na1][2], o[na1][3],
                         ph[0], ph[1], ph[2], ph[3], v2h, v3h);
                mma_bf16(o[na1][0], o[na1][1], o[na1][2], o[na1][3],
                         ph[0], ph[1], ph[2], ph[3], v2l, v3l);
                mma_bf16(o[na1][0], o[na1][1], o[na1][2], o[na1][3],
                         pl[0], pl[1], pl[2], pl[3], v2h, v3h);
            }
        }
    }

    // ---- epilogue: divide by l, write split bf16 context ----
    const float inv0 = 1.f / l0, inv1 = 1.f / l1;
    const int r0 = i0 + wid * 16 + g;
#pragma unroll
    for (int na = 0; na < 8; na++) {
        const int col = na * 8 + q * 2;
        const size_t p0 = base + (size_t)r0 * DD + col;
        const size_t p1 = base + (size_t)(r0 + 8) * DD + col;
        uint32_t hh, ll;
        split2(o[na][0] * inv0, o[na][1] * inv0, hh, ll);
        *(uint32_t*)(Chi + p0) = hh;
        *(uint32_t*)(Clo + p0) = ll;
        split2(o[na][2] * inv1, o[na][3] * inv1, hh, ll);
        *(uint32_t*)(Chi + p1) = hh;
        *(uint32_t*)(Clo + p1) = ll;
    }
}

// ============================================================================
// kernel_launch
// ============================================================================
extern "C" void kernel_launch(void* const* d_in, const int* in_sizes, int n_in,
                              void* d_out, int out_size)
{
    const float* q    = (const float*)d_in[0];
    const float* k    = (const float*)d_in[1];
    const float* v    = (const float*)d_in[2];
    const int*   mask = (const int*)  d_in[3];
    const float* wq   = (const float*)d_in[4];
    const float* bq   = (const float*)d_in[5];
    const float* wk   = (const float*)d_in[6];
    const float* bk   = (const float*)d_in[7];
    const float* wv   = (const float*)d_in[8];
    const float* bv   = (const float*)d_in[9];
    const float* wo   = (const float*)d_in[10];
    const float* bo   = (const float*)d_in[11];
    float* out = (float*)d_out;

    __nv_bfloat16 *ahi, *alo, *whi, *wlo;
    __nv_bfloat16 *qhi, *qlo, *khi, *klo, *vhi, *vlo, *chi, *clo;
    cudaGetSymbolAddress((void**)&ahi, g_Ahi);
    cudaGetSymbolAddress((void**)&alo, g_Alo);
    cudaGetSymbolAddress((void**)&whi, g_Whi);
    cudaGetSymbolAddress((void**)&wlo, g_Wlo);
    cudaGetSymbolAddress((void**)&qhi, g_Qhi);
    cudaGetSymbolAddress((void**)&qlo, g_Qlo);
    cudaGetSymbolAddress((void**)&khi, g_Khi);
    cudaGetSymbolAddress((void**)&klo, g_Klo);
    cudaGetSymbolAddress((void**)&vhi, g_Vhi);
    cudaGetSymbolAddress((void**)&vlo, g_Vlo);
    cudaGetSymbolAddress((void**)&chi, g_Chi);
    cudaGetSymbolAddress((void**)&clo, g_Clo);

    static bool attr_set = false;
    if (!attr_set) {
        cudaFuncSetAttribute(flash_tc, cudaFuncAttributeMaxDynamicSharedMemorySize,
                             FLASH_SMEM_BYTES);
        cudaFuncSetAttribute(gemm_tc, cudaFuncAttributeMaxDynamicSharedMemorySize,
                             GS_TOTAL);
        attr_set = true;
    }

    const int nA4 = NROWS * DD / 4;
    const int nW4 = DD * DD / 4;
    dim3 tgrid(DD / 128, NROWS / 128);   // (8, 32)

    // Q projection -> split bf16
    split_bf16<<<nA4 / 256, 256>>>(q, ahi, alo, nA4);
    split_bf16<<<nW4 / 256, 256>>>(wq, whi, wlo, nW4);
    gemm_tc<<<tgrid, 256, GS_TOTAL>>>(ahi, alo, whi, wlo, bq, nullptr, qhi, qlo, NROWS, DD, DD, 1);
    // K projection
    split_bf16<<<nA4 / 256, 256>>>(k, ahi, alo, nA4);
    split_bf16<<<nW4 / 256, 256>>>(wk, whi, wlo, nW4);
    gemm_tc<<<tgrid, 256, GS_TOTAL>>>(ahi, alo, whi, wlo, bk, nullptr, khi, klo, NROWS, DD, DD, 1);
    // V projection
    split_bf16<<<nA4 / 256, 256>>>(v, ahi, alo, nA4);
    split_bf16<<<nW4 / 256, 256>>>(wv, whi, wlo, nW4);
    gemm_tc<<<tgrid, 256, GS_TOTAL>>>(ahi, alo, whi, wlo, bv, nullptr, vhi, vlo, NROWS, DD, DD, 1);

    // Attention (writes split bf16 context directly)
    dim3 fgrid(SS / 128, HH, BB);        // (16, 16, 2)
    flash_tc<<<fgrid, 256, FLASH_SMEM_BYTES>>>(qhi, qlo, khi, klo, vhi, vlo, mask, chi, clo);

    // Output projection (fp32 out)
    split_bf16<<<nW4 / 256, 256>>>(wo, whi, wlo, nW4);
    gemm_tc<<<tgrid, 256, GS_TOTAL>>>(chi, clo, whi, wlo, bo, out, nullptr, nullptr, NROWS, DD, DD, 0);
}